// round 4
// baseline (speedup 1.0000x reference)
#include <cuda_runtime.h>
#include <cuda_fp16.h>

// Problem constants
#define Bz 16
#define Nn 5000
#define Ff 64
#define Hh 32
#define Ee 160000
#define ETOT (Ee + Nn)         // edges + self loops = 165000
#define Kdim (Nn * Hh)         // 160000
#define NHID 512
#define NACT 16
#define KSPLIT 148

// -------- scratch (device globals; no allocation allowed) --------
__device__ int    g_is64;
__device__ int    g_deg[Nn];
__device__ int    g_cursor[Nn];
__device__ int    g_off[Nn + 1];
__device__ float  g_dinv[Nn];
__device__ int    g_srcs[ETOT];
__device__ float  g_nrms[ETOT];
__device__ __half g_xw1[Bz * Nn * Hh];   // 5.12 MB
__device__ __half g_xw2[Bz * Nn * Hh];   // 5.12 MB
__device__ float  g_h2[Bz * Nn * Hh];    // 10.24 MB (MLP input)
__device__ float  g_hid[Bz * NHID];      // MLP hidden partials

__device__ __forceinline__ int edge_at(const void* ei, int idx) {
    if (g_is64) return (int)((const long long*)ei)[idx];
    return ((const int*)ei)[idx];
}

// ================= setup =================

__global__ void init_k(const unsigned int* __restrict__ ei) {
    int i = blockIdx.x * blockDim.x + threadIdx.x;
    if (i == 0) {
        int all0 = 1;
        for (int k = 0; k < 64; k++)
            if (ei[2 * k + 1] != 0u) { all0 = 0; break; }
        g_is64 = all0;
    }
    if (i < Nn) { g_deg[i] = 1; g_cursor[i] = 0; }
    if (i < Bz * NHID) g_hid[i] = 0.0f;
}

// 4 edges per thread -> 4 independent atomic chains
__global__ void hist_k(const void* __restrict__ ei) {
    int i = blockIdx.x * blockDim.x + threadIdx.x;
    int e0 = i * 4;
    int d[4];
#pragma unroll
    for (int q = 0; q < 4; q++)
        d[q] = (e0 + q < Ee) ? edge_at(ei, Ee + e0 + q) : -1;
#pragma unroll
    for (int q = 0; q < 4; q++)
        if (d[q] >= 0) atomicAdd(&g_deg[d[q]], 1);
}

// single block: dinv + exclusive scan of degrees (warp-shuffle based)
__global__ void scan_k() {
    __shared__ int wsum[32];
    int t = threadIdx.x, lane = t & 31, wid = t >> 5;
    const int CH = 5;
    int base = t * CH;
    int d[CH];
    int local = 0;
#pragma unroll
    for (int j = 0; j < CH; j++) {
        int idx = base + j;
        d[j] = (idx < Nn) ? g_deg[idx] : 0;
        local += d[j];
    }
    int incl = local;
#pragma unroll
    for (int off = 1; off < 32; off <<= 1) {
        int v = __shfl_up_sync(0xffffffffu, incl, off);
        if (lane >= off) incl += v;
    }
    if (lane == 31) wsum[wid] = incl;
    __syncthreads();
    if (wid == 0) {
        int iv = wsum[lane];
#pragma unroll
        for (int off = 1; off < 32; off <<= 1) {
            int u = __shfl_up_sync(0xffffffffu, iv, off);
            if (lane >= off) iv += u;
        }
        wsum[lane] = iv;
    }
    __syncthreads();
    int excl = (wid ? wsum[wid - 1] : 0) + (incl - local);
#pragma unroll
    for (int j = 0; j < CH; j++) {
        int idx = base + j;
        if (idx < Nn) {
            g_off[idx] = excl;
            excl += d[j];
            g_dinv[idx] = rsqrtf((float)d[j]);
        }
    }
    if (t == 1023) g_off[Nn] = wsum[31];
}

// 4 items per thread -> 4 independent ATOMG chains
__global__ void scatter_k(const void* __restrict__ ei) {
    int i = blockIdx.x * blockDim.x + threadIdx.x;
    int i0 = i * 4;
    int s[4], d[4];
    float nm[4];
#pragma unroll
    for (int q = 0; q < 4; q++) {
        int idx = i0 + q;
        if (idx >= ETOT) { d[q] = -1; continue; }
        if (idx < Ee) { s[q] = edge_at(ei, idx); d[q] = edge_at(ei, Ee + idx); }
        else          { s[q] = d[q] = idx - Ee; }
        nm[q] = g_dinv[s[q]] * g_dinv[d[q]];
    }
    int pos[4];
#pragma unroll
    for (int q = 0; q < 4; q++)
        if (d[q] >= 0) pos[q] = g_off[d[q]] + atomicAdd(&g_cursor[d[q]], 1);
#pragma unroll
    for (int q = 0; q < 4; q++)
        if (d[q] >= 0) { g_srcs[pos[q]] = s[q]; g_nrms[pos[q]] = nm[q]; }
}

// ============ layer1 GEMM: xw1[r,32] = feat[r,64] @ W1, fp16 out ============
__global__ __launch_bounds__(256) void gemm1_k(
    const float* __restrict__ X, const float* __restrict__ W,
    __half* __restrict__ Y)
{
    const int F = Ff;
    __shared__ float sx[64 * Ff];
    __shared__ float sw[Ff * 32];
    int tid = threadIdx.x;
    for (int i = tid; i < F * 32; i += 256) sw[i] = W[i];
    long long r0 = (long long)blockIdx.x * 64;
    for (int i = tid; i < 64 * F; i += 256) {
        int r = i >> 6, c = i & 63;
        sx[r * F + c] = X[(r0 + r) * F + c];
    }
    __syncthreads();
    int h = tid & 31;
    int g = tid >> 5;
    float acc[8] = {0.f, 0.f, 0.f, 0.f, 0.f, 0.f, 0.f, 0.f};
    for (int f = 0; f < F; f++) {
        float w = sw[f * 32 + h];
#pragma unroll
        for (int i = 0; i < 8; i++)
            acc[i] = fmaf(sx[(g * 8 + i) * F + f], w, acc[i]);
    }
#pragma unroll
    for (int i = 0; i < 8; i++)
        Y[(r0 + g * 8 + i) * 32 + h] = __float2half(acc[i]);
}

#define SEDGE 512   // smem-staged edge capacity per node (max degree safety fallback below)

// ===== agg1 fused with layer2 transform; half2 gather, 2 edges per step =====
__global__ __launch_bounds__(512) void agg1_fuse_k(
    const __half* __restrict__ xw, const float* __restrict__ b1,
    const float* __restrict__ W2, __half* __restrict__ out2)
{
    __shared__ float sW2[32 * 32];
    __shared__ int   s_src[SEDGE];
    __shared__ float s_nrm[SEDGE];
    int tid = threadIdx.x;
    int n = blockIdx.x;
    for (int i = tid; i < 1024; i += 512) sW2[i] = W2[i];
    int beg = g_off[n], cnt = g_off[n + 1] - beg;
    int scnt = min(cnt, SEDGE);
    for (int i = tid; i < scnt; i += 512) {
        s_src[i] = g_srcs[beg + i];
        s_nrm[i] = g_nrms[beg + i];
    }
    __syncthreads();

    int b = tid >> 5, lane = tid & 31;
    int el = lane >> 4, hh = (lane & 15) * 2;
    const __half* xb = xw + (size_t)b * (Nn * Hh);

    float2 accA = {0.f, 0.f}, accB = {0.f, 0.f};
    for (int e = 0; e < cnt; e += 4) {
        int i0 = e + el, i1 = e + 2 + el;
        float m0 = 0.f, m1 = 0.f; int s0 = 0, s1 = 0;
        if (i0 < cnt) { if (i0 < SEDGE) { s0 = s_src[i0]; m0 = s_nrm[i0]; }
                        else { s0 = g_srcs[beg + i0]; m0 = g_nrms[beg + i0]; } }
        if (i1 < cnt) { if (i1 < SEDGE) { s1 = s_src[i1]; m1 = s_nrm[i1]; }
                        else { s1 = g_srcs[beg + i1]; m1 = g_nrms[beg + i1]; } }
        float2 v0 = __half22float2(*(const __half2*)(xb + s0 * 32 + hh));
        float2 v1 = __half22float2(*(const __half2*)(xb + s1 * 32 + hh));
        accA.x = fmaf(m0, v0.x, accA.x);  accA.y = fmaf(m0, v0.y, accA.y);
        accB.x = fmaf(m1, v1.x, accB.x);  accB.y = fmaf(m1, v1.y, accB.y);
    }
    float2 acc = { accA.x + accB.x, accA.y + accB.y };
    acc.x += __shfl_xor_sync(0xffffffffu, acc.x, 16);
    acc.y += __shfl_xor_sync(0xffffffffu, acc.y, 16);
    acc.x = fmaxf(acc.x + b1[hh], 0.f);
    acc.y = fmaxf(acc.y + b1[hh + 1], 0.f);

    // xw2 row = h1row @ W2 (h-values live as float2 on lanes 0..15)
    float o = 0.f;
#pragma unroll
    for (int q = 0; q < 16; q++) {
        float hx = __shfl_sync(0xffffffffu, acc.x, q);
        float hy = __shfl_sync(0xffffffffu, acc.y, q);
        o = fmaf(hx, sW2[(2 * q) * 32 + lane], o);
        o = fmaf(hy, sW2[(2 * q + 1) * 32 + lane], o);
    }
    out2[((size_t)b * Nn + n) * 32 + lane] = __float2half(o);
}

// ===== agg2: h2 = relu(agg(xw2) + b2), fp32 out (float2 stores) =====
__global__ __launch_bounds__(512) void agg2_k(
    const __half* __restrict__ xw, const float* __restrict__ bias,
    float* __restrict__ out)
{
    __shared__ int   s_src[SEDGE];
    __shared__ float s_nrm[SEDGE];
    int tid = threadIdx.x;
    int n = blockIdx.x;
    int beg = g_off[n], cnt = g_off[n + 1] - beg;
    int scnt = min(cnt, SEDGE);
    for (int i = tid; i < scnt; i += 512) {
        s_src[i] = g_srcs[beg + i];
        s_nrm[i] = g_nrms[beg + i];
    }
    __syncthreads();

    int b = tid >> 5, lane = tid & 31;
    int el = lane >> 4, hh = (lane & 15) * 2;
    const __half* xb = xw + (size_t)b * (Nn * Hh);

    float2 accA = {0.f, 0.f}, accB = {0.f, 0.f};
    for (int e = 0; e < cnt; e += 4) {
        int i0 = e + el, i1 = e + 2 + el;
        float m0 = 0.f, m1 = 0.f; int s0 = 0, s1 = 0;
        if (i0 < cnt) { if (i0 < SEDGE) { s0 = s_src[i0]; m0 = s_nrm[i0]; }
                        else { s0 = g_srcs[beg + i0]; m0 = g_nrms[beg + i0]; } }
        if (i1 < cnt) { if (i1 < SEDGE) { s1 = s_src[i1]; m1 = s_nrm[i1]; }
                        else { s1 = g_srcs[beg + i1]; m1 = g_nrms[beg + i1]; } }
        float2 v0 = __half22float2(*(const __half2*)(xb + s0 * 32 + hh));
        float2 v1 = __half22float2(*(const __half2*)(xb + s1 * 32 + hh));
        accA.x = fmaf(m0, v0.x, accA.x);  accA.y = fmaf(m0, v0.y, accA.y);
        accB.x = fmaf(m1, v1.x, accB.x);  accB.y = fmaf(m1, v1.y, accB.y);
    }
    float2 acc = { accA.x + accB.x, accA.y + accB.y };
    acc.x += __shfl_xor_sync(0xffffffffu, acc.x, 16);
    acc.y += __shfl_xor_sync(0xffffffffu, acc.y, 16);
    if (el == 0) {
        float2 r;
        r.x = fmaxf(acc.x + bias[hh], 0.f);
        r.y = fmaxf(acc.y + bias[hh + 1], 0.f);
        *(float2*)(out + ((size_t)b * Nn + n) * 32 + hh) = r;
    }
}

// ===== big MLP GEMM: split-K=148, 512 threads, zero-mov FFMA2 inner loop =====
__global__ __launch_bounds__(512) void mlp1_k(
    const float* __restrict__ flat, const float* __restrict__ Wp1)
{
    __shared__ __align__(16) unsigned long long sfd[128][16];  // (f,f) pairs, 16KB
    int tid = threadIdx.x;
    int bg = (tid >> 7) * 4;             // batch group of 4
    int c4 = (tid & 127) * 4;            // columns c4 .. c4+3
    const int chunk = (Kdim + KSPLIT - 1) / KSPLIT;   // 1082
    int k0 = blockIdx.x * chunk;
    int k1 = min(k0 + chunk, Kdim);

    unsigned long long acc[2][4];
#pragma unroll
    for (int i = 0; i < 2; i++)
#pragma unroll
        for (int j = 0; j < 4; j++) acc[i][j] = 0ull;

    for (int kt = k0; kt < k1; kt += 128) {
        int kn = min(128, k1 - kt);
        __syncthreads();
#pragma unroll
        for (int idx = tid; idx < 2048; idx += 512) {
            int b = idx >> 7, kk = idx & 127;
            float v = (kk < kn) ? flat[(size_t)b * Kdim + kt + kk] : 0.0f;
            unsigned long long p;
            asm("mov.b64 %0, {%1, %1};" : "=l"(p) : "r"(__float_as_uint(v)));
            sfd[kk][b] = p;
        }
        __syncthreads();
        const ulonglong2* wp = (const ulonglong2*)(Wp1 + (size_t)kt * NHID + c4);
        for (int kk = 0; kk < kn; kk++) {
            ulonglong2 w = __ldcs(wp);       // cols (c4,c4+1) and (c4+2,c4+3) as pairs
            wp += NHID / 4;                  // next k row: 512 floats = 128 ulonglong2
#pragma unroll
            for (int j = 0; j < 4; j++) {
                unsigned long long f = sfd[kk][bg + j];
                asm("fma.rn.f32x2 %0, %1, %2, %0;" : "+l"(acc[0][j]) : "l"(w.x), "l"(f));
                asm("fma.rn.f32x2 %0, %1, %2, %0;" : "+l"(acc[1][j]) : "l"(w.y), "l"(f));
            }
        }
    }
#pragma unroll
    for (int i = 0; i < 2; i++)
#pragma unroll
        for (int j = 0; j < 4; j++) {
            float2 v = *(float2*)&acc[i][j];     // cols (c4+2i, c4+2i+1), batch bg+j
            atomicAdd(&g_hid[(bg + j) * NHID + c4 + 2 * i],     v.x);
            atomicAdd(&g_hid[(bg + j) * NHID + c4 + 2 * i + 1], v.y);
        }
}

// ===== final: relu(hid+bp1) @ Wp2 + bp2, one block per batch =====
__global__ __launch_bounds__(512) void mlp2_k(
    const float* __restrict__ bp1, const float* __restrict__ Wp2,
    const float* __restrict__ bp2, float* __restrict__ out)
{
    __shared__ float part[16][NACT];
    int b = blockIdx.x;
    int j = threadIdx.x;
    int wid = j >> 5, lane = j & 31;
    float hv = fmaxf(g_hid[b * NHID + j] + bp1[j], 0.0f);
    float acc[NACT];
#pragma unroll
    for (int a = 0; a < NACT; a++) acc[a] = hv * Wp2[j * NACT + a];
#pragma unroll
    for (int off = 16; off; off >>= 1)
#pragma unroll
        for (int a = 0; a < NACT; a++)
            acc[a] += __shfl_down_sync(0xffffffffu, acc[a], off);
    if (lane == 0)
#pragma unroll
        for (int a = 0; a < NACT; a++) part[wid][a] = acc[a];
    __syncthreads();
    if (j < NACT) {
        float s = bp2[j];
#pragma unroll
        for (int w = 0; w < 16; w++) s += part[w][j];
        out[b * NACT + j] = s;
    }
}

// ================= launch =================
extern "C" void kernel_launch(void* const* d_in, const int* in_sizes, int n_in,
                              void* d_out, int out_size)
{
    const float* features = (const float*)d_in[0];
    const void*  edge     = d_in[1];
    const float* W1  = (const float*)d_in[2];
    const float* b1  = (const float*)d_in[3];
    const float* W2  = (const float*)d_in[4];
    const float* b2  = (const float*)d_in[5];
    const float* Wp1 = (const float*)d_in[6];
    const float* bp1 = (const float*)d_in[7];
    const float* Wp2 = (const float*)d_in[8];
    const float* bp2 = (const float*)d_in[9];
    float* out = (float*)d_out;

    __half* xw1; cudaGetSymbolAddress((void**)&xw1, g_xw1);
    __half* xw2; cudaGetSymbolAddress((void**)&xw2, g_xw2);
    float*  h2;  cudaGetSymbolAddress((void**)&h2,  g_h2);

    init_k<<<(Bz * NHID + 255) / 256, 256>>>((const unsigned int*)edge);
    hist_k<<<(Ee / 4 + 255) / 256, 256>>>(edge);
    scan_k<<<1, 1024>>>();
    scatter_k<<<((ETOT + 3) / 4 + 255) / 256, 256>>>(edge);   // profiled slot

    gemm1_k<<<(Bz * Nn) / 64, 256>>>(features, W1, xw1);
    agg1_fuse_k<<<Nn, 512>>>(xw1, b1, W2, xw2);
    agg2_k<<<Nn, 512>>>(xw2, b2, h2);

    mlp1_k<<<KSPLIT, 512>>>(h2, Wp1);
    mlp2_k<<<Bz, 512>>>(bp1, Wp2, bp2, out);
}

// round 5
// speedup vs baseline: 1.0262x; 1.0262x over previous
#include <cuda_runtime.h>
#include <cuda_fp16.h>

// Problem constants
#define Bz 16
#define Nn 5000
#define Ff 64
#define Hh 32
#define Ee 160000
#define ETOT (Ee + Nn)         // edges + self loops = 165000
#define Kdim (Nn * Hh)         // 160000
#define NHID 512
#define NACT 16
#define KSPLIT 148

// -------- scratch (device globals; no allocation allowed) --------
__device__ int    g_is64;
__device__ int    g_deg[Nn];
__device__ int    g_cursor[Nn];
__device__ int    g_off[Nn + 1];
__device__ float  g_dinv[Nn];
__device__ int    g_srcs[ETOT];
__device__ float  g_nrms[ETOT];
__device__ __half g_xw1[Bz * Nn * Hh];   // 5.12 MB
__device__ __half g_xw2[Bz * Nn * Hh];   // 5.12 MB
__device__ float  g_h2[Bz * Nn * Hh];    // 10.24 MB (MLP input)
__device__ float  g_hid[Bz * NHID];      // MLP hidden partials

__device__ __forceinline__ int edge_at(const void* ei, int idx) {
    if (g_is64) return (int)((const long long*)ei)[idx];
    return ((const int*)ei)[idx];
}

// ================= setup =================

__global__ void init_k(const unsigned int* __restrict__ ei) {
    int i = blockIdx.x * blockDim.x + threadIdx.x;
    if (i == 0) {
        int all0 = 1;
        for (int k = 0; k < 64; k++)
            if (ei[2 * k + 1] != 0u) { all0 = 0; break; }
        g_is64 = all0;
    }
    if (i < Nn) { g_deg[i] = 1; g_cursor[i] = 0; }
    if (i < Bz * NHID) g_hid[i] = 0.0f;
}

__global__ void hist_k(const void* __restrict__ ei) {
    int e = blockIdx.x * blockDim.x + threadIdx.x;
    if (e < Ee) atomicAdd(&g_deg[edge_at(ei, Ee + e)], 1);
}

// single block: dinv + exclusive scan of degrees (warp-shuffle based)
__global__ void scan_k() {
    __shared__ int wsum[32];
    int t = threadIdx.x, lane = t & 31, wid = t >> 5;
    const int CH = 5;
    int base = t * CH;
    int d[CH];
    int local = 0;
#pragma unroll
    for (int j = 0; j < CH; j++) {
        int idx = base + j;
        d[j] = (idx < Nn) ? g_deg[idx] : 0;
        local += d[j];
    }
    int incl = local;
#pragma unroll
    for (int off = 1; off < 32; off <<= 1) {
        int v = __shfl_up_sync(0xffffffffu, incl, off);
        if (lane >= off) incl += v;
    }
    if (lane == 31) wsum[wid] = incl;
    __syncthreads();
    if (wid == 0) {
        int iv = wsum[lane];
#pragma unroll
        for (int off = 1; off < 32; off <<= 1) {
            int u = __shfl_up_sync(0xffffffffu, iv, off);
            if (lane >= off) iv += u;
        }
        wsum[lane] = iv;
    }
    __syncthreads();
    int excl = (wid ? wsum[wid - 1] : 0) + (incl - local);
#pragma unroll
    for (int j = 0; j < CH; j++) {
        int idx = base + j;
        if (idx < Nn) {
            g_off[idx] = excl;
            excl += d[j];
            g_dinv[idx] = rsqrtf((float)d[j]);
        }
    }
    if (t == 1023) g_off[Nn] = wsum[31];
}

__global__ void scatter_k(const void* __restrict__ ei) {
    int i = blockIdx.x * blockDim.x + threadIdx.x;
    if (i >= ETOT) return;
    int s, d;
    if (i < Ee) { s = edge_at(ei, i); d = edge_at(ei, Ee + i); }
    else        { s = d = i - Ee; }
    float nm = g_dinv[s] * g_dinv[d];
    int pos = g_off[d] + atomicAdd(&g_cursor[d], 1);
    g_srcs[pos] = s;
    g_nrms[pos] = nm;
}

// ============ layer1 GEMM: xw1[r,32] = feat[r,64] @ W1, fp16 out ============
__global__ __launch_bounds__(256) void gemm1_k(
    const float* __restrict__ X, const float* __restrict__ W,
    __half* __restrict__ Y)
{
    const int F = Ff;
    __shared__ float sx[64 * Ff];
    __shared__ float sw[Ff * 32];
    int tid = threadIdx.x;
    for (int i = tid; i < F * 32; i += 256) sw[i] = W[i];
    long long r0 = (long long)blockIdx.x * 64;
    for (int i = tid; i < 64 * F; i += 256) {
        int r = i >> 6, c = i & 63;
        sx[r * F + c] = X[(r0 + r) * F + c];
    }
    __syncthreads();
    int h = tid & 31;
    int g = tid >> 5;
    float acc[8] = {0.f, 0.f, 0.f, 0.f, 0.f, 0.f, 0.f, 0.f};
    for (int f = 0; f < F; f++) {
        float w = sw[f * 32 + h];
#pragma unroll
        for (int i = 0; i < 8; i++)
            acc[i] = fmaf(sx[(g * 8 + i) * F + f], w, acc[i]);
    }
#pragma unroll
    for (int i = 0; i < 8; i++)
        Y[(r0 + g * 8 + i) * 32 + h] = __float2half(acc[i]);
}

#define SEDGE 512   // smem-staged edge capacity per node

// ===== agg1 fused with layer2 transform; half2 gather, 2 edges per step =====
__global__ __launch_bounds__(512) void agg1_fuse_k(
    const __half* __restrict__ xw, const float* __restrict__ b1,
    const float* __restrict__ W2, __half* __restrict__ out2)
{
    __shared__ float sW2[32 * 32];
    __shared__ int   s_src[SEDGE];
    __shared__ float s_nrm[SEDGE];
    int tid = threadIdx.x;
    int n = blockIdx.x;
    for (int i = tid; i < 1024; i += 512) sW2[i] = W2[i];
    int beg = g_off[n], cnt = g_off[n + 1] - beg;
    int scnt = min(cnt, SEDGE);
    for (int i = tid; i < scnt; i += 512) {
        s_src[i] = g_srcs[beg + i];
        s_nrm[i] = g_nrms[beg + i];
    }
    __syncthreads();

    int b = tid >> 5, lane = tid & 31;
    int el = lane >> 4, hh = (lane & 15) * 2;
    const __half* xb = xw + (size_t)b * (Nn * Hh);

    float2 accA = {0.f, 0.f}, accB = {0.f, 0.f};
    for (int e = 0; e < cnt; e += 4) {
        int i0 = e + el, i1 = e + 2 + el;
        float m0 = 0.f, m1 = 0.f; int s0 = 0, s1 = 0;
        if (i0 < cnt) { if (i0 < SEDGE) { s0 = s_src[i0]; m0 = s_nrm[i0]; }
                        else { s0 = g_srcs[beg + i0]; m0 = g_nrms[beg + i0]; } }
        if (i1 < cnt) { if (i1 < SEDGE) { s1 = s_src[i1]; m1 = s_nrm[i1]; }
                        else { s1 = g_srcs[beg + i1]; m1 = g_nrms[beg + i1]; } }
        float2 v0 = __half22float2(*(const __half2*)(xb + s0 * 32 + hh));
        float2 v1 = __half22float2(*(const __half2*)(xb + s1 * 32 + hh));
        accA.x = fmaf(m0, v0.x, accA.x);  accA.y = fmaf(m0, v0.y, accA.y);
        accB.x = fmaf(m1, v1.x, accB.x);  accB.y = fmaf(m1, v1.y, accB.y);
    }
    float2 acc = { accA.x + accB.x, accA.y + accB.y };
    acc.x += __shfl_xor_sync(0xffffffffu, acc.x, 16);
    acc.y += __shfl_xor_sync(0xffffffffu, acc.y, 16);
    acc.x = fmaxf(acc.x + b1[hh], 0.f);
    acc.y = fmaxf(acc.y + b1[hh + 1], 0.f);

    // xw2 row = h1row @ W2 (h-values live as float2 on lanes 0..15)
    float o = 0.f;
#pragma unroll
    for (int q = 0; q < 16; q++) {
        float hx = __shfl_sync(0xffffffffu, acc.x, q);
        float hy = __shfl_sync(0xffffffffu, acc.y, q);
        o = fmaf(hx, sW2[(2 * q) * 32 + lane], o);
        o = fmaf(hy, sW2[(2 * q + 1) * 32 + lane], o);
    }
    out2[((size_t)b * Nn + n) * 32 + lane] = __float2half(o);
}

// ===== agg2: h2 = relu(agg(xw2) + b2), fp32 out (float2 stores) =====
__global__ __launch_bounds__(512) void agg2_k(
    const __half* __restrict__ xw, const float* __restrict__ bias,
    float* __restrict__ out)
{
    __shared__ int   s_src[SEDGE];
    __shared__ float s_nrm[SEDGE];
    int tid = threadIdx.x;
    int n = blockIdx.x;
    int beg = g_off[n], cnt = g_off[n + 1] - beg;
    int scnt = min(cnt, SEDGE);
    for (int i = tid; i < scnt; i += 512) {
        s_src[i] = g_srcs[beg + i];
        s_nrm[i] = g_nrms[beg + i];
    }
    __syncthreads();

    int b = tid >> 5, lane = tid & 31;
    int el = lane >> 4, hh = (lane & 15) * 2;
    const __half* xb = xw + (size_t)b * (Nn * Hh);

    float2 accA = {0.f, 0.f}, accB = {0.f, 0.f};
    for (int e = 0; e < cnt; e += 4) {
        int i0 = e + el, i1 = e + 2 + el;
        float m0 = 0.f, m1 = 0.f; int s0 = 0, s1 = 0;
        if (i0 < cnt) { if (i0 < SEDGE) { s0 = s_src[i0]; m0 = s_nrm[i0]; }
                        else { s0 = g_srcs[beg + i0]; m0 = g_nrms[beg + i0]; } }
        if (i1 < cnt) { if (i1 < SEDGE) { s1 = s_src[i1]; m1 = s_nrm[i1]; }
                        else { s1 = g_srcs[beg + i1]; m1 = g_nrms[beg + i1]; } }
        float2 v0 = __half22float2(*(const __half2*)(xb + s0 * 32 + hh));
        float2 v1 = __half22float2(*(const __half2*)(xb + s1 * 32 + hh));
        accA.x = fmaf(m0, v0.x, accA.x);  accA.y = fmaf(m0, v0.y, accA.y);
        accB.x = fmaf(m1, v1.x, accB.x);  accB.y = fmaf(m1, v1.y, accB.y);
    }
    float2 acc = { accA.x + accB.x, accA.y + accB.y };
    acc.x += __shfl_xor_sync(0xffffffffu, acc.x, 16);
    acc.y += __shfl_xor_sync(0xffffffffu, acc.y, 16);
    if (el == 0) {
        float2 r;
        r.x = fmaxf(acc.x + bias[hh], 0.f);
        r.y = fmaxf(acc.y + bias[hh + 1], 0.f);
        *(float2*)(out + ((size_t)b * Nn + n) * 32 + hh) = r;
    }
}

// ===== big MLP GEMM: split-K=148, thread = 1 unique column x 16 batches =====
// Weight line read exactly ONCE chip-wide: 512 threads cover all 512 columns.
__global__ __launch_bounds__(512) void mlp1_k(
    const float* __restrict__ flat, const float* __restrict__ Wp1)
{
    __shared__ __align__(16) unsigned long long sfd[128][8];  // (b2p,b2p+1) pairs, 8KB
    int tid = threadIdx.x;
    const int chunk = (Kdim + KSPLIT - 1) / KSPLIT;   // 1082
    int k0 = blockIdx.x * chunk;
    int k1 = min(k0 + chunk, Kdim);

    unsigned long long acc[8];
#pragma unroll
    for (int j = 0; j < 8; j++) acc[j] = 0ull;

    for (int kt = k0; kt < k1; kt += 128) {
        int kn = min(128, k1 - kt);
        __syncthreads();
        // pack batch pairs: sfd[kk][p] = (flat[2p][kt+kk], flat[2p+1][kt+kk])
#pragma unroll
        for (int idx = tid; idx < 1024; idx += 512) {
            int p = idx >> 7, kk = idx & 127;
            float a = 0.f, bvl = 0.f;
            if (kk < kn) {
                a   = flat[(size_t)(2 * p)     * Kdim + kt + kk];
                bvl = flat[(size_t)(2 * p + 1) * Kdim + kt + kk];
            }
            unsigned long long pr;
            asm("mov.b64 %0, {%1, %2};" : "=l"(pr)
                : "r"(__float_as_uint(a)), "r"(__float_as_uint(bvl)));
            sfd[kk][p] = pr;
        }
        __syncthreads();
        const float* wp = Wp1 + (size_t)kt * NHID + tid;
#pragma unroll 2
        for (int kk = 0; kk < kn; kk++) {
            float w = __ldcs(wp);
            wp += NHID;
            unsigned long long wd;
            asm("mov.b64 %0, {%1, %1};" : "=l"(wd) : "r"(__float_as_uint(w)));
            const ulonglong2* f2 = (const ulonglong2*)sfd[kk];
#pragma unroll
            for (int q = 0; q < 4; q++) {
                ulonglong2 f = f2[q];
                asm("fma.rn.f32x2 %0, %1, %2, %0;" : "+l"(acc[2*q])   : "l"(wd), "l"(f.x));
                asm("fma.rn.f32x2 %0, %1, %2, %0;" : "+l"(acc[2*q+1]) : "l"(wd), "l"(f.y));
            }
        }
    }
#pragma unroll
    for (int j = 0; j < 8; j++) {
        float2 v = *(float2*)&acc[j];     // batches (2j, 2j+1), column tid
        atomicAdd(&g_hid[(2 * j)     * NHID + tid], v.x);
        atomicAdd(&g_hid[(2 * j + 1) * NHID + tid], v.y);
    }
}

// ===== final: relu(hid+bp1) @ Wp2 + bp2, one block per batch =====
__global__ __launch_bounds__(512) void mlp2_k(
    const float* __restrict__ bp1, const float* __restrict__ Wp2,
    const float* __restrict__ bp2, float* __restrict__ out)
{
    __shared__ float part[16][NACT];
    int b = blockIdx.x;
    int j = threadIdx.x;
    int wid = j >> 5, lane = j & 31;
    float hv = fmaxf(g_hid[b * NHID + j] + bp1[j], 0.0f);
    float acc[NACT];
#pragma unroll
    for (int a = 0; a < NACT; a++) acc[a] = hv * Wp2[j * NACT + a];
#pragma unroll
    for (int off = 16; off; off >>= 1)
#pragma unroll
        for (int a = 0; a < NACT; a++)
            acc[a] += __shfl_down_sync(0xffffffffu, acc[a], off);
    if (lane == 0)
#pragma unroll
        for (int a = 0; a < NACT; a++) part[wid][a] = acc[a];
    __syncthreads();
    if (j < NACT) {
        float s = bp2[j];
#pragma unroll
        for (int w = 0; w < 16; w++) s += part[w][j];
        out[b * NACT + j] = s;
    }
}

// ================= launch =================
extern "C" void kernel_launch(void* const* d_in, const int* in_sizes, int n_in,
                              void* d_out, int out_size)
{
    const float* features = (const float*)d_in[0];
    const void*  edge     = d_in[1];
    const float* W1  = (const float*)d_in[2];
    const float* b1  = (const float*)d_in[3];
    const float* W2  = (const float*)d_in[4];
    const float* b2  = (const float*)d_in[5];
    const float* Wp1 = (const float*)d_in[6];
    const float* bp1 = (const float*)d_in[7];
    const float* Wp2 = (const float*)d_in[8];
    const float* bp2 = (const float*)d_in[9];
    float* out = (float*)d_out;

    __half* xw1; cudaGetSymbolAddress((void**)&xw1, g_xw1);
    __half* xw2; cudaGetSymbolAddress((void**)&xw2, g_xw2);
    float*  h2;  cudaGetSymbolAddress((void**)&h2,  g_h2);

    init_k<<<(Bz * NHID + 255) / 256, 256>>>((const unsigned int*)edge);
    hist_k<<<(Ee + 255) / 256, 256>>>(edge);
    scan_k<<<1, 1024>>>();
    scatter_k<<<(ETOT + 255) / 256, 256>>>(edge);

    gemm1_k<<<(Bz * Nn) / 64, 256>>>(features, W1, xw1);
    agg1_fuse_k<<<Nn, 512>>>(xw1, b1, W2, xw2);
    agg2_k<<<Nn, 512>>>(xw2, b2, h2);

    mlp1_k<<<KSPLIT, 512>>>(h2, Wp1);
    mlp2_k<<<Bz, 512>>>(bp1, Wp2, bp2, out);
}

// round 6
// speedup vs baseline: 1.3708x; 1.3358x over previous
#include <cuda_runtime.h>
#include <cuda_fp16.h>

// Problem constants
#define Bz 16
#define Nn 5000
#define Ff 64
#define Hh 32
#define Ee 160000
#define ETOT (Ee + Nn)         // edges + self loops = 165000
#define Kdim (Nn * Hh)         // 160000
#define NHID 512
#define NACT 16
#define KSPLIT 148

// -------- scratch (device globals; no allocation allowed) --------
__device__ int    g_is64;
__device__ int    g_deg[Nn];
__device__ int    g_cursor[Nn];
__device__ int    g_off[Nn + 1];
__device__ float  g_dinv[Nn];
__device__ int    g_srcs[ETOT];
__device__ float  g_nrms[ETOT];
__device__ __half g_xw1[Bz * Nn * Hh];   // 5.12 MB
__device__ __half g_xw2[Bz * Nn * Hh];   // 5.12 MB
__device__ float  g_h2[Bz * Nn * Hh];    // 10.24 MB (MLP input)
__device__ float  g_hid[Bz * NHID];      // MLP hidden partials

__device__ __forceinline__ int edge_at(const void* ei, int idx) {
    if (g_is64) return (int)((const long long*)ei)[idx];
    return ((const int*)ei)[idx];
}

// ================= setup =================

__global__ void init_k(const unsigned int* __restrict__ ei) {
    int i = blockIdx.x * blockDim.x + threadIdx.x;
    if (i == 0) {
        int all0 = 1;
        for (int k = 0; k < 64; k++)
            if (ei[2 * k + 1] != 0u) { all0 = 0; break; }
        g_is64 = all0;
    }
    if (i < Nn) { g_deg[i] = 1; g_cursor[i] = 0; }
    if (i < Bz * NHID) g_hid[i] = 0.0f;
}

__global__ void hist_k(const void* __restrict__ ei) {
    int e = blockIdx.x * blockDim.x + threadIdx.x;
    if (e < Ee) atomicAdd(&g_deg[edge_at(ei, Ee + e)], 1);
}

// single block: dinv + exclusive scan of degrees (warp-shuffle based)
__global__ void scan_k() {
    __shared__ int wsum[32];
    int t = threadIdx.x, lane = t & 31, wid = t >> 5;
    const int CH = 5;
    int base = t * CH;
    int d[CH];
    int local = 0;
#pragma unroll
    for (int j = 0; j < CH; j++) {
        int idx = base + j;
        d[j] = (idx < Nn) ? g_deg[idx] : 0;
        local += d[j];
    }
    int incl = local;
#pragma unroll
    for (int off = 1; off < 32; off <<= 1) {
        int v = __shfl_up_sync(0xffffffffu, incl, off);
        if (lane >= off) incl += v;
    }
    if (lane == 31) wsum[wid] = incl;
    __syncthreads();
    if (wid == 0) {
        int iv = wsum[lane];
#pragma unroll
        for (int off = 1; off < 32; off <<= 1) {
            int u = __shfl_up_sync(0xffffffffu, iv, off);
            if (lane >= off) iv += u;
        }
        wsum[lane] = iv;
    }
    __syncthreads();
    int excl = (wid ? wsum[wid - 1] : 0) + (incl - local);
#pragma unroll
    for (int j = 0; j < CH; j++) {
        int idx = base + j;
        if (idx < Nn) {
            g_off[idx] = excl;
            excl += d[j];
            g_dinv[idx] = rsqrtf((float)d[j]);
        }
    }
    if (t == 1023) g_off[Nn] = wsum[31];
}

__global__ void scatter_k(const void* __restrict__ ei) {
    int i = blockIdx.x * blockDim.x + threadIdx.x;
    if (i >= ETOT) return;
    int s, d;
    if (i < Ee) { s = edge_at(ei, i); d = edge_at(ei, Ee + i); }
    else        { s = d = i - Ee; }
    float nm = g_dinv[s] * g_dinv[d];
    int pos = g_off[d] + atomicAdd(&g_cursor[d], 1);
    g_srcs[pos] = s;
    g_nrms[pos] = nm;
}

// ============ layer1 GEMM: xw1[r,32] = feat[r,64] @ W1, fp16 out ============
__global__ __launch_bounds__(256) void gemm1_k(
    const float* __restrict__ X, const float* __restrict__ W,
    __half* __restrict__ Y)
{
    const int F = Ff;
    __shared__ float sx[64 * Ff];
    __shared__ float sw[Ff * 32];
    int tid = threadIdx.x;
    for (int i = tid; i < F * 32; i += 256) sw[i] = W[i];
    long long r0 = (long long)blockIdx.x * 64;
    for (int i = tid; i < 64 * F; i += 256) {
        int r = i >> 6, c = i & 63;
        sx[r * F + c] = X[(r0 + r) * F + c];
    }
    __syncthreads();
    int h = tid & 31;
    int g = tid >> 5;
    float acc[8] = {0.f, 0.f, 0.f, 0.f, 0.f, 0.f, 0.f, 0.f};
    for (int f = 0; f < F; f++) {
        float w = sw[f * 32 + h];
#pragma unroll
        for (int i = 0; i < 8; i++)
            acc[i] = fmaf(sx[(g * 8 + i) * F + f], w, acc[i]);
    }
#pragma unroll
    for (int i = 0; i < 8; i++)
        Y[(r0 + g * 8 + i) * 32 + h] = __float2half(acc[i]);
}

// ===== agg1 fused with layer2 transform (R3 known-good form):
//   h1 = relu(agg(xw1) + b1); xw2 = h1 @ W2   (per warp = one (node,batch) row)
__global__ __launch_bounds__(512) void agg1_fuse_k(
    const __half* __restrict__ xw, const float* __restrict__ b1,
    const float* __restrict__ W2, __half* __restrict__ out2)
{
    __shared__ float sW2[32 * 32];
    int tid = threadIdx.x;
    for (int i = tid; i < 1024; i += 512) sW2[i] = W2[i];
    __syncthreads();

    int n = blockIdx.x;
    int b = tid >> 5;
    int lane = tid & 31;
    int beg = g_off[n], end = g_off[n + 1];
    const __half* xb = xw + (size_t)b * (Nn * Hh);
    float a0 = 0.f, a1 = 0.f, a2 = 0.f, a3 = 0.f;
    int e = beg;
    for (; e + 4 <= end; e += 4) {
        int s0 = g_srcs[e], s1 = g_srcs[e + 1], s2 = g_srcs[e + 2], s3 = g_srcs[e + 3];
        float m0 = g_nrms[e], m1 = g_nrms[e + 1], m2 = g_nrms[e + 2], m3 = g_nrms[e + 3];
        a0 = fmaf(m0, __half2float(xb[s0 * 32 + lane]), a0);
        a1 = fmaf(m1, __half2float(xb[s1 * 32 + lane]), a1);
        a2 = fmaf(m2, __half2float(xb[s2 * 32 + lane]), a2);
        a3 = fmaf(m3, __half2float(xb[s3 * 32 + lane]), a3);
    }
    for (; e < end; e++)
        a0 = fmaf(g_nrms[e], __half2float(xb[g_srcs[e] * 32 + lane]), a0);
    float h = fmaxf((a0 + a1) + (a2 + a3) + b1[lane], 0.0f);

    // xw2 row = h1row @ W2 via lane broadcast
    float o = 0.f;
#pragma unroll
    for (int f = 0; f < 32; f++) {
        float hf = __shfl_sync(0xffffffffu, h, f);
        o = fmaf(hf, sW2[f * 32 + lane], o);
    }
    out2[((size_t)b * Nn + n) * 32 + lane] = __float2half(o);
}

// ===== agg2: h2 = relu(agg(xw2) + b2), fp32 out (R3 known-good form) =====
__global__ __launch_bounds__(512) void agg2_k(
    const __half* __restrict__ xw, const float* __restrict__ bias,
    float* __restrict__ out)
{
    int n = blockIdx.x;
    int b = threadIdx.x >> 5;
    int lane = threadIdx.x & 31;
    int beg = g_off[n], end = g_off[n + 1];
    const __half* xb = xw + (size_t)b * (Nn * Hh);
    float a0 = 0.f, a1 = 0.f, a2 = 0.f, a3 = 0.f;
    int e = beg;
    for (; e + 4 <= end; e += 4) {
        int s0 = g_srcs[e], s1 = g_srcs[e + 1], s2 = g_srcs[e + 2], s3 = g_srcs[e + 3];
        float m0 = g_nrms[e], m1 = g_nrms[e + 1], m2 = g_nrms[e + 2], m3 = g_nrms[e + 3];
        a0 = fmaf(m0, __half2float(xb[s0 * 32 + lane]), a0);
        a1 = fmaf(m1, __half2float(xb[s1 * 32 + lane]), a1);
        a2 = fmaf(m2, __half2float(xb[s2 * 32 + lane]), a2);
        a3 = fmaf(m3, __half2float(xb[s3 * 32 + lane]), a3);
    }
    for (; e < end; e++)
        a0 = fmaf(g_nrms[e], __half2float(xb[g_srcs[e] * 32 + lane]), a0);
    float r = (a0 + a1) + (a2 + a3) + bias[lane];
    out[((size_t)b * Nn + n) * 32 + lane] = fmaxf(r, 0.0f);
}

// ===== big MLP GEMM: 4 k-groups x 128 threads; LDG.128 weights (1x traffic),
//       depth-2 prefetch; batch pairs broadcast from smem; FFMA2 accum =====
__global__ __launch_bounds__(512) void mlp1_k(
    const float* __restrict__ flat, const float* __restrict__ Wp1)
{
    __shared__ __align__(16) unsigned long long sfd[128][8];  // (b2p,b2p+1) per kk
    int tid = threadIdx.x;
    int kg = tid >> 7;                    // k-group 0..3 (handles kk ≡ kg mod 4)
    int c4 = (tid & 127) * 4;             // columns c4..c4+3
    const int chunk = (Kdim + KSPLIT - 1) / KSPLIT;   // 1082
    int k0 = blockIdx.x * chunk;
    int k1 = min(k0 + chunk, Kdim);

    unsigned long long acc[4][8];         // [col][batch-pair]
#pragma unroll
    for (int c = 0; c < 4; c++)
#pragma unroll
        for (int p = 0; p < 8; p++) acc[c][p] = 0ull;

    for (int kt = k0; kt < k1; kt += 128) {
        int kn = min(128, k1 - kt);
        __syncthreads();
        // stage batch pairs: sfd[kk][p] = (flat[2p][kt+kk], flat[2p+1][kt+kk])
#pragma unroll
        for (int idx = tid; idx < 1024; idx += 512) {
            int p = idx >> 7, kk = idx & 127;
            float a = 0.f, bv = 0.f;
            if (kk < kn) {
                a  = flat[(size_t)(2 * p)     * Kdim + kt + kk];
                bv = flat[(size_t)(2 * p + 1) * Kdim + kt + kk];
            }
            unsigned long long pr;
            asm("mov.b64 %0, {%1, %2};" : "=l"(pr)
                : "r"(__float_as_uint(a)), "r"(__float_as_uint(bv)));
            sfd[kk][p] = pr;
        }
        __syncthreads();

        // k-group kg: kk = kg, kg+4, ... < kn; weight row read once per block.
        const float4* wp = (const float4*)(Wp1 + (size_t)(kt + kg) * NHID + c4);
        const float4 zero4 = make_float4(0.f, 0.f, 0.f, 0.f);
        float4 w0 = (kg     < kn) ? __ldcs(wp)       : zero4;
        float4 w1 = (kg + 4 < kn) ? __ldcs(wp + 512) : zero4;   // 512 float4 = 4 rows
        const float4* wpn = wp + 1024;
        for (int kk = kg; kk < kn; kk += 4) {
            float4 wn = (kk + 8 < kn) ? __ldcs(wpn) : zero4;
            wpn += 512;
            unsigned long long wd[4];
            asm("mov.b64 %0, {%1, %1};" : "=l"(wd[0]) : "r"(__float_as_uint(w0.x)));
            asm("mov.b64 %0, {%1, %1};" : "=l"(wd[1]) : "r"(__float_as_uint(w0.y)));
            asm("mov.b64 %0, {%1, %1};" : "=l"(wd[2]) : "r"(__float_as_uint(w0.z)));
            asm("mov.b64 %0, {%1, %1};" : "=l"(wd[3]) : "r"(__float_as_uint(w0.w)));
            const ulonglong2* f2 = (const ulonglong2*)sfd[kk];
#pragma unroll
            for (int q = 0; q < 4; q++) {
                ulonglong2 f = f2[q];             // pairs 2q, 2q+1 (broadcast LDS.128)
#pragma unroll
                for (int c = 0; c < 4; c++) {
                    asm("fma.rn.f32x2 %0, %1, %2, %0;"
                        : "+l"(acc[c][2 * q])     : "l"(wd[c]), "l"(f.x));
                    asm("fma.rn.f32x2 %0, %1, %2, %0;"
                        : "+l"(acc[c][2 * q + 1]) : "l"(wd[c]), "l"(f.y));
                }
            }
            w0 = w1; w1 = wn;
        }
    }
#pragma unroll
    for (int c = 0; c < 4; c++)
#pragma unroll
        for (int p = 0; p < 8; p++) {
            float2 v = *(float2*)&acc[c][p];      // batches (2p,2p+1), col c4+c
            atomicAdd(&g_hid[(2 * p)     * NHID + c4 + c], v.x);
            atomicAdd(&g_hid[(2 * p + 1) * NHID + c4 + c], v.y);
        }
}

// ===== final: relu(hid+bp1) @ Wp2 + bp2, one block per batch =====
__global__ __launch_bounds__(512) void mlp2_k(
    const float* __restrict__ bp1, const float* __restrict__ Wp2,
    const float* __restrict__ bp2, float* __restrict__ out)
{
    __shared__ float part[16][NACT];
    int b = blockIdx.x;
    int j = threadIdx.x;
    int wid = j >> 5, lane = j & 31;
    float hv = fmaxf(g_hid[b * NHID + j] + bp1[j], 0.0f);
    float acc[NACT];
#pragma unroll
    for (int a = 0; a < NACT; a++) acc[a] = hv * Wp2[j * NACT + a];
#pragma unroll
    for (int off = 16; off; off >>= 1)
#pragma unroll
        for (int a = 0; a < NACT; a++)
            acc[a] += __shfl_down_sync(0xffffffffu, acc[a], off);
    if (lane == 0)
#pragma unroll
        for (int a = 0; a < NACT; a++) part[wid][a] = acc[a];
    __syncthreads();
    if (j < NACT) {
        float s = bp2[j];
#pragma unroll
        for (int w = 0; w < 16; w++) s += part[w][j];
        out[b * NACT + j] = s;
    }
}

// ================= launch =================
extern "C" void kernel_launch(void* const* d_in, const int* in_sizes, int n_in,
                              void* d_out, int out_size)
{
    const float* features = (const float*)d_in[0];
    const void*  edge     = d_in[1];
    const float* W1  = (const float*)d_in[2];
    const float* b1  = (const float*)d_in[3];
    const float* W2  = (const float*)d_in[4];
    const float* b2  = (const float*)d_in[5];
    const float* Wp1 = (const float*)d_in[6];
    const float* bp1 = (const float*)d_in[7];
    const float* Wp2 = (const float*)d_in[8];
    const float* bp2 = (const float*)d_in[9];
    float* out = (float*)d_out;

    __half* xw1; cudaGetSymbolAddress((void**)&xw1, g_xw1);
    __half* xw2; cudaGetSymbolAddress((void**)&xw2, g_xw2);
    float*  h2;  cudaGetSymbolAddress((void**)&h2,  g_h2);

    init_k<<<(Bz * NHID + 255) / 256, 256>>>((const unsigned int*)edge);
    hist_k<<<(Ee + 255) / 256, 256>>>(edge);
    scan_k<<<1, 1024>>>();
    scatter_k<<<(ETOT + 255) / 256, 256>>>(edge);

    gemm1_k<<<(Bz * Nn) / 64, 256>>>(features, W1, xw1);
    agg1_fuse_k<<<Nn, 512>>>(xw1, b1, W2, xw2);
    agg2_k<<<Nn, 512>>>(xw2, b2, h2);

    mlp1_k<<<KSPLIT, 512>>>(h2, Wp1);
    mlp2_k<<<Bz, 512>>>(bp1, Wp2, bp2, out);
}

// round 7
// speedup vs baseline: 1.5627x; 1.1400x over previous
#include <cuda_runtime.h>
#include <cuda_fp16.h>
#include <cuda_pipeline.h>

// Problem constants
#define Bz 16
#define Nn 5000
#define Ff 64
#define Hh 32
#define Ee 160000
#define ETOT (Ee + Nn)         // edges + self loops = 165000
#define Kdim (Nn * Hh)         // 160000
#define NHID 512
#define NACT 16
#define KSPLIT 148
#define CHUNK 1088             // k-rows per block (multiple of 16), 148*1088 >= Kdim
#define CH 16                  // k-rows per cp.async stage
#define NST 4                  // stages (ring)

// -------- scratch (device globals; no allocation allowed) --------
__device__ int    g_is64;
__device__ int    g_deg[Nn];
__device__ int    g_cursor[Nn];
__device__ int    g_off[Nn + 1];
__device__ float  g_dinv[Nn];
__device__ int    g_srcs[ETOT];
__device__ float  g_nrms[ETOT];
__device__ __half g_xw1[Bz * Nn * Hh];   // 5.12 MB
__device__ __half g_xw2[Bz * Nn * Hh];   // 5.12 MB
__device__ float  g_h2[Bz * Nn * Hh];    // 10.24 MB (MLP input)
__device__ float  g_hid[Bz * NHID];      // MLP hidden partials

__device__ __forceinline__ int edge_at(const void* ei, int idx) {
    if (g_is64) return (int)((const long long*)ei)[idx];
    return ((const int*)ei)[idx];
}

// ================= setup =================

__global__ void init_k(const unsigned int* __restrict__ ei) {
    int i = blockIdx.x * blockDim.x + threadIdx.x;
    if (i == 0) {
        int all0 = 1;
        for (int k = 0; k < 64; k++)
            if (ei[2 * k + 1] != 0u) { all0 = 0; break; }
        g_is64 = all0;
    }
    if (i < Nn) { g_deg[i] = 1; g_cursor[i] = 0; }
    if (i < Bz * NHID) g_hid[i] = 0.0f;
}

__global__ void hist_k(const void* __restrict__ ei) {
    int e = blockIdx.x * blockDim.x + threadIdx.x;
    if (e < Ee) atomicAdd(&g_deg[edge_at(ei, Ee + e)], 1);
}

// single block: dinv + exclusive scan of degrees (warp-shuffle based)
__global__ void scan_k() {
    __shared__ int wsum[32];
    int t = threadIdx.x, lane = t & 31, wid = t >> 5;
    const int CHD = 5;
    int base = t * CHD;
    int d[CHD];
    int local = 0;
#pragma unroll
    for (int j = 0; j < CHD; j++) {
        int idx = base + j;
        d[j] = (idx < Nn) ? g_deg[idx] : 0;
        local += d[j];
    }
    int incl = local;
#pragma unroll
    for (int off = 1; off < 32; off <<= 1) {
        int v = __shfl_up_sync(0xffffffffu, incl, off);
        if (lane >= off) incl += v;
    }
    if (lane == 31) wsum[wid] = incl;
    __syncthreads();
    if (wid == 0) {
        int iv = wsum[lane];
#pragma unroll
        for (int off = 1; off < 32; off <<= 1) {
            int u = __shfl_up_sync(0xffffffffu, iv, off);
            if (lane >= off) iv += u;
        }
        wsum[lane] = iv;
    }
    __syncthreads();
    int excl = (wid ? wsum[wid - 1] : 0) + (incl - local);
#pragma unroll
    for (int j = 0; j < CHD; j++) {
        int idx = base + j;
        if (idx < Nn) {
            g_off[idx] = excl;
            excl += d[j];
            g_dinv[idx] = rsqrtf((float)d[j]);
        }
    }
    if (t == 1023) g_off[Nn] = wsum[31];
}

__global__ void scatter_k(const void* __restrict__ ei) {
    int i = blockIdx.x * blockDim.x + threadIdx.x;
    if (i >= ETOT) return;
    int s, d;
    if (i < Ee) { s = edge_at(ei, i); d = edge_at(ei, Ee + i); }
    else        { s = d = i - Ee; }
    float nm = g_dinv[s] * g_dinv[d];
    int pos = g_off[d] + atomicAdd(&g_cursor[d], 1);
    g_srcs[pos] = s;
    g_nrms[pos] = nm;
}

// ============ layer1 GEMM: xw1[r,32] = feat[r,64] @ W1, fp16 out ============
__global__ __launch_bounds__(256) void gemm1_k(
    const float* __restrict__ X, const float* __restrict__ W,
    __half* __restrict__ Y)
{
    const int F = Ff;
    __shared__ float sx[64 * Ff];
    __shared__ float sw[Ff * 32];
    int tid = threadIdx.x;
    for (int i = tid; i < F * 32; i += 256) sw[i] = W[i];
    long long r0 = (long long)blockIdx.x * 64;
    for (int i = tid; i < 64 * F; i += 256) {
        int r = i >> 6, c = i & 63;
        sx[r * F + c] = X[(r0 + r) * F + c];
    }
    __syncthreads();
    int h = tid & 31;
    int g = tid >> 5;
    float acc[8] = {0.f, 0.f, 0.f, 0.f, 0.f, 0.f, 0.f, 0.f};
    for (int f = 0; f < F; f++) {
        float w = sw[f * 32 + h];
#pragma unroll
        for (int i = 0; i < 8; i++)
            acc[i] = fmaf(sx[(g * 8 + i) * F + f], w, acc[i]);
    }
#pragma unroll
    for (int i = 0; i < 8; i++)
        Y[(r0 + g * 8 + i) * 32 + h] = __float2half(acc[i]);
}

// ===== agg1 fused with layer2 transform (known-good R3 form) =====
__global__ __launch_bounds__(512) void agg1_fuse_k(
    const __half* __restrict__ xw, const float* __restrict__ b1,
    const float* __restrict__ W2, __half* __restrict__ out2)
{
    __shared__ float sW2[32 * 32];
    int tid = threadIdx.x;
    for (int i = tid; i < 1024; i += 512) sW2[i] = W2[i];
    __syncthreads();

    int n = blockIdx.x;
    int b = tid >> 5;
    int lane = tid & 31;
    int beg = g_off[n], end = g_off[n + 1];
    const __half* xb = xw + (size_t)b * (Nn * Hh);
    float a0 = 0.f, a1 = 0.f, a2 = 0.f, a3 = 0.f;
    int e = beg;
    for (; e + 4 <= end; e += 4) {
        int s0 = g_srcs[e], s1 = g_srcs[e + 1], s2 = g_srcs[e + 2], s3 = g_srcs[e + 3];
        float m0 = g_nrms[e], m1 = g_nrms[e + 1], m2 = g_nrms[e + 2], m3 = g_nrms[e + 3];
        a0 = fmaf(m0, __half2float(xb[s0 * 32 + lane]), a0);
        a1 = fmaf(m1, __half2float(xb[s1 * 32 + lane]), a1);
        a2 = fmaf(m2, __half2float(xb[s2 * 32 + lane]), a2);
        a3 = fmaf(m3, __half2float(xb[s3 * 32 + lane]), a3);
    }
    for (; e < end; e++)
        a0 = fmaf(g_nrms[e], __half2float(xb[g_srcs[e] * 32 + lane]), a0);
    float h = fmaxf((a0 + a1) + (a2 + a3) + b1[lane], 0.0f);

    float o = 0.f;
#pragma unroll
    for (int f = 0; f < 32; f++) {
        float hf = __shfl_sync(0xffffffffu, h, f);
        o = fmaf(hf, sW2[f * 32 + lane], o);
    }
    out2[((size_t)b * Nn + n) * 32 + lane] = __float2half(o);
}

// ===== agg2: h2 = relu(agg(xw2) + b2), fp32 out (known-good R3 form) =====
__global__ __launch_bounds__(512) void agg2_k(
    const __half* __restrict__ xw, const float* __restrict__ bias,
    float* __restrict__ out)
{
    int n = blockIdx.x;
    int b = threadIdx.x >> 5;
    int lane = threadIdx.x & 31;
    int beg = g_off[n], end = g_off[n + 1];
    const __half* xb = xw + (size_t)b * (Nn * Hh);
    float a0 = 0.f, a1 = 0.f, a2 = 0.f, a3 = 0.f;
    int e = beg;
    for (; e + 4 <= end; e += 4) {
        int s0 = g_srcs[e], s1 = g_srcs[e + 1], s2 = g_srcs[e + 2], s3 = g_srcs[e + 3];
        float m0 = g_nrms[e], m1 = g_nrms[e + 1], m2 = g_nrms[e + 2], m3 = g_nrms[e + 3];
        a0 = fmaf(m0, __half2float(xb[s0 * 32 + lane]), a0);
        a1 = fmaf(m1, __half2float(xb[s1 * 32 + lane]), a1);
        a2 = fmaf(m2, __half2float(xb[s2 * 32 + lane]), a2);
        a3 = fmaf(m3, __half2float(xb[s3 * 32 + lane]), a3);
    }
    for (; e < end; e++)
        a0 = fmaf(g_nrms[e], __half2float(xb[g_srcs[e] * 32 + lane]), a0);
    float r = (a0 + a1) + (a2 + a3) + bias[lane];
    out[((size_t)b * Nn + n) * 32 + lane] = fmaxf(r, 0.0f);
}

// ===== big MLP GEMM: cp.async 4-stage smem pipeline for weights =====
// 512 threads: k-group g = tid>>7 handles rows r ≡ g (mod 4); c4 = (tid&127)*4.
// Weight DRAM traffic exactly 1x chip-wide; async engine keeps ~96KB in flight.
__global__ __launch_bounds__(512) void mlp1_k(
    const float* __restrict__ flat, const float* __restrict__ Wp1)
{
    extern __shared__ __align__(16) unsigned char dsm[];
    float* wbuf = (float*)dsm;                               // NST * CH * 512 floats
    unsigned long long* sbat =
        (unsigned long long*)(dsm + NST * CH * NHID * 4);    // [128][8] pairs

    int tid = threadIdx.x;
    int kg = tid >> 7;
    int c4 = (tid & 127) * 4;
    int k0 = blockIdx.x * CHUNK;
    int k1 = min(k0 + CHUNK, Kdim);
    int nch = (k1 - k0 + CH - 1) / CH;

    unsigned long long acc[4][8];        // [col][batch-pair]
#pragma unroll
    for (int c = 0; c < 4; c++)
#pragma unroll
        for (int p = 0; p < 8; p++) acc[c][p] = 0ull;

    // ---- async stage issue: chunk c -> ring slot c&3 (16 rows x 2KB) ----
    // all threads call this with the same c; commit is uniform.
#define ISSUE_STAGE(cc)                                                        \
    do {                                                                       \
        int _c = (cc);                                                         \
        if (_c < nch) {                                                        \
            int _kb = k0 + _c * CH;                                            \
            float* _dst = wbuf + (_c & (NST - 1)) * (CH * NHID);               \
            _Pragma("unroll")                                                  \
            for (int _i = 0; _i < 4; _i++) {                                   \
                int _idx = tid + 512 * _i;                                     \
                int _r = _idx >> 7;                                            \
                int _cc4 = (_idx & 127) * 4;                                   \
                int _k = _kb + _r;                                             \
                if (_k < k1)                                                   \
                    __pipeline_memcpy_async(_dst + _r * NHID + _cc4,           \
                                            Wp1 + (size_t)_k * NHID + _cc4,    \
                                            16);                               \
            }                                                                  \
            __pipeline_commit();                                               \
        }                                                                      \
    } while (0)

    ISSUE_STAGE(0);
    ISSUE_STAGE(1);
    ISSUE_STAGE(2);

    for (int c = 0; c < nch; c++) {
        __pipeline_wait_prior(2);       // stage c arrived (per-thread)
        __syncthreads();                // publish across threads; compute c-1 done

        int kbase = k0 + c * CH;
        if ((c & 7) == 0) {
            // stage batch pairs for 128-row tile [kbase, kbase+128)
            int kt = kbase;
            int kn = min(128, k1 - kt);
#pragma unroll
            for (int idx = tid; idx < 1024; idx += 512) {
                int p = idx >> 7, kk = idx & 127;
                float a = 0.f, bv = 0.f;
                if (kk < kn) {
                    a  = flat[(size_t)(2 * p)     * Kdim + kt + kk];
                    bv = flat[(size_t)(2 * p + 1) * Kdim + kt + kk];
                }
                unsigned long long pr;
                asm("mov.b64 %0, {%1, %2};" : "=l"(pr)
                    : "r"(__float_as_uint(a)), "r"(__float_as_uint(bv)));
                sbat[kk * 8 + p] = pr;
            }
            __syncthreads();
        }

        ISSUE_STAGE(c + 3);             // refill ring slot (c+3)&3 = (c-1)&3

        // compute chunk c: rows kg, kg+4, kg+8, kg+12
        const float* wst = wbuf + (c & (NST - 1)) * (CH * NHID);
#pragma unroll
        for (int rr = 0; rr < 4; rr++) {
            int r = kg + rr * 4;
            int k = kbase + r;
            if (k >= k1) continue;
            float4 w = *(const float4*)(wst + r * NHID + c4);
            unsigned long long wd[4];
            asm("mov.b64 %0, {%1, %1};" : "=l"(wd[0]) : "r"(__float_as_uint(w.x)));
            asm("mov.b64 %0, {%1, %1};" : "=l"(wd[1]) : "r"(__float_as_uint(w.y)));
            asm("mov.b64 %0, {%1, %1};" : "=l"(wd[2]) : "r"(__float_as_uint(w.z)));
            asm("mov.b64 %0, {%1, %1};" : "=l"(wd[3]) : "r"(__float_as_uint(w.w)));
            int kk = (c & 7) * CH + r;
            const ulonglong2* f2 = (const ulonglong2*)(sbat + kk * 8);
#pragma unroll
            for (int q = 0; q < 4; q++) {
                ulonglong2 f = f2[q];       // broadcast LDS.128
#pragma unroll
                for (int cc = 0; cc < 4; cc++) {
                    asm("fma.rn.f32x2 %0, %1, %2, %0;"
                        : "+l"(acc[cc][2 * q])     : "l"(wd[cc]), "l"(f.x));
                    asm("fma.rn.f32x2 %0, %1, %2, %0;"
                        : "+l"(acc[cc][2 * q + 1]) : "l"(wd[cc]), "l"(f.y));
                }
            }
        }
    }
    __pipeline_wait_prior(0);
#undef ISSUE_STAGE

#pragma unroll
    for (int cc = 0; cc < 4; cc++)
#pragma unroll
        for (int p = 0; p < 8; p++) {
            float2 v = *(float2*)&acc[cc][p];    // batches (2p,2p+1), col c4+cc
            atomicAdd(&g_hid[(2 * p)     * NHID + c4 + cc], v.x);
            atomicAdd(&g_hid[(2 * p + 1) * NHID + c4 + cc], v.y);
        }
}

// ===== final: relu(hid+bp1) @ Wp2 + bp2, one block per batch =====
__global__ __launch_bounds__(512) void mlp2_k(
    const float* __restrict__ bp1, const float* __restrict__ Wp2,
    const float* __restrict__ bp2, float* __restrict__ out)
{
    __shared__ float part[16][NACT];
    int b = blockIdx.x;
    int j = threadIdx.x;
    int wid = j >> 5, lane = j & 31;
    float hv = fmaxf(g_hid[b * NHID + j] + bp1[j], 0.0f);
    float acc[NACT];
#pragma unroll
    for (int a = 0; a < NACT; a++) acc[a] = hv * Wp2[j * NACT + a];
#pragma unroll
    for (int off = 16; off; off >>= 1)
#pragma unroll
        for (int a = 0; a < NACT; a++)
            acc[a] += __shfl_down_sync(0xffffffffu, acc[a], off);
    if (lane == 0)
#pragma unroll
        for (int a = 0; a < NACT; a++) part[wid][a] = acc[a];
    __syncthreads();
    if (j < NACT) {
        float s = bp2[j];
#pragma unroll
        for (int w = 0; w < 16; w++) s += part[w][j];
        out[b * NACT + j] = s;
    }
}

// ================= launch =================
extern "C" void kernel_launch(void* const* d_in, const int* in_sizes, int n_in,
                              void* d_out, int out_size)
{
    const float* features = (const float*)d_in[0];
    const void*  edge     = d_in[1];
    const float* W1  = (const float*)d_in[2];
    const float* b1  = (const float*)d_in[3];
    const float* W2  = (const float*)d_in[4];
    const float* b2  = (const float*)d_in[5];
    const float* Wp1 = (const float*)d_in[6];
    const float* bp1 = (const float*)d_in[7];
    const float* Wp2 = (const float*)d_in[8];
    const float* bp2 = (const float*)d_in[9];
    float* out = (float*)d_out;

    __half* xw1; cudaGetSymbolAddress((void**)&xw1, g_xw1);
    __half* xw2; cudaGetSymbolAddress((void**)&xw2, g_xw2);
    float*  h2;  cudaGetSymbolAddress((void**)&h2,  g_h2);

    init_k<<<(Bz * NHID + 255) / 256, 256>>>((const unsigned int*)edge);
    hist_k<<<(Ee + 255) / 256, 256>>>(edge);
    scan_k<<<1, 1024>>>();
    scatter_k<<<(ETOT + 255) / 256, 256>>>(edge);

    gemm1_k<<<(Bz * Nn) / 64, 256>>>(features, W1, xw1);
    agg1_fuse_k<<<Nn, 512>>>(xw1, b1, W2, xw2);
    agg2_k<<<Nn, 512>>>(xw2, b2, h2);

    size_t smem = (size_t)NST * CH * NHID * 4 + 128 * 8 * 8;   // 131072 + 8192
    cudaFuncSetAttribute(mlp1_k, cudaFuncAttributeMaxDynamicSharedMemorySize,
                         (int)smem);
    mlp1_k<<<KSPLIT, 512, smem>>>(h2, Wp1);
    mlp2_k<<<Bz, 512>>>(bp1, Wp2, bp2, out);
}

// round 8
// speedup vs baseline: 1.6637x; 1.0646x over previous
#include <cuda_runtime.h>
#include <cuda_fp16.h>

// Problem constants
#define Bz 16
#define Nn 5000
#define Ff 64
#define Hh 32
#define Ee 160000
#define ETOT (Ee + Nn)         // edges + self loops = 165000
#define Kdim (Nn * Hh)         // 160000
#define NHID 512
#define NACT 16
#define KSPLIT 148
#define CHUNK 1088             // k-rows per block (multiple of 16), 148*1088 >= Kdim
#define CH 16                  // k-rows per TMA stage (32 KB contiguous)
#define NST 4                  // ring stages
#define STAGE_BYTES (CH * NHID * 4)   // 32768

// -------- scratch (device globals; no allocation allowed) --------
__device__ int    g_is64;
__device__ int    g_deg[Nn];
__device__ int    g_cursor[Nn];
__device__ int    g_off[Nn + 1];
__device__ float  g_dinv[Nn];
__device__ int    g_srcs[ETOT];
__device__ float  g_nrms[ETOT];
__device__ __half g_xw1[Bz * Nn * Hh];   // 5.12 MB
__device__ __half g_xw2[Bz * Nn * Hh];   // 5.12 MB
__device__ float  g_h2[Bz * Nn * Hh];    // 10.24 MB (MLP input)
__device__ float  g_hid[Bz * NHID];      // MLP hidden partials

__device__ __forceinline__ int edge_at(const void* ei, int idx) {
    if (g_is64) return (int)((const long long*)ei)[idx];
    return ((const int*)ei)[idx];
}

__device__ __forceinline__ unsigned smem_u32(const void* p) {
    unsigned a;
    asm("{ .reg .u64 t; cvta.to.shared.u64 t, %1; cvt.u32.u64 %0, t; }"
        : "=r"(a) : "l"(p));
    return a;
}

__device__ __forceinline__ void mbar_wait_parity(unsigned mbar, unsigned parity) {
    asm volatile(
        "{\n\t.reg .pred P;\n"
        "LW_%=:\n\t"
        "mbarrier.try_wait.parity.acquire.cta.shared::cta.b64 P, [%0], %1, 0x989680;\n\t"
        "@P bra LD_%=;\n\t"
        "bra LW_%=;\n"
        "LD_%=:\n\t}"
        :: "r"(mbar), "r"(parity) : "memory");
}

// ================= setup =================

__global__ void init_k(const unsigned int* __restrict__ ei) {
    int i = blockIdx.x * blockDim.x + threadIdx.x;
    if (i == 0) {
        int all0 = 1;
        for (int k = 0; k < 64; k++)
            if (ei[2 * k + 1] != 0u) { all0 = 0; break; }
        g_is64 = all0;
    }
    if (i < Nn) { g_deg[i] = 1; g_cursor[i] = 0; }
    if (i < Bz * NHID) g_hid[i] = 0.0f;
}

__global__ void hist_k(const void* __restrict__ ei) {
    int e = blockIdx.x * blockDim.x + threadIdx.x;
    if (e < Ee) atomicAdd(&g_deg[edge_at(ei, Ee + e)], 1);
}

// single block: dinv + exclusive scan of degrees (warp-shuffle based)
__global__ void scan_k() {
    __shared__ int wsum[32];
    int t = threadIdx.x, lane = t & 31, wid = t >> 5;
    const int CHD = 5;
    int base = t * CHD;
    int d[CHD];
    int local = 0;
#pragma unroll
    for (int j = 0; j < CHD; j++) {
        int idx = base + j;
        d[j] = (idx < Nn) ? g_deg[idx] : 0;
        local += d[j];
    }
    int incl = local;
#pragma unroll
    for (int off = 1; off < 32; off <<= 1) {
        int v = __shfl_up_sync(0xffffffffu, incl, off);
        if (lane >= off) incl += v;
    }
    if (lane == 31) wsum[wid] = incl;
    __syncthreads();
    if (wid == 0) {
        int iv = wsum[lane];
#pragma unroll
        for (int off = 1; off < 32; off <<= 1) {
            int u = __shfl_up_sync(0xffffffffu, iv, off);
            if (lane >= off) iv += u;
        }
        wsum[lane] = iv;
    }
    __syncthreads();
    int excl = (wid ? wsum[wid - 1] : 0) + (incl - local);
#pragma unroll
    for (int j = 0; j < CHD; j++) {
        int idx = base + j;
        if (idx < Nn) {
            g_off[idx] = excl;
            excl += d[j];
            g_dinv[idx] = rsqrtf((float)d[j]);
        }
    }
    if (t == 1023) g_off[Nn] = wsum[31];
}

__global__ void scatter_k(const void* __restrict__ ei) {
    int i = blockIdx.x * blockDim.x + threadIdx.x;
    if (i >= ETOT) return;
    int s, d;
    if (i < Ee) { s = edge_at(ei, i); d = edge_at(ei, Ee + i); }
    else        { s = d = i - Ee; }
    float nm = g_dinv[s] * g_dinv[d];
    int pos = g_off[d] + atomicAdd(&g_cursor[d], 1);
    g_srcs[pos] = s;
    g_nrms[pos] = nm;
}

// ============ layer1 GEMM: xw1[r,32] = feat[r,64] @ W1, fp16 out ============
__global__ __launch_bounds__(256) void gemm1_k(
    const float* __restrict__ X, const float* __restrict__ W,
    __half* __restrict__ Y)
{
    const int F = Ff;
    __shared__ float sx[64 * Ff];
    __shared__ float sw[Ff * 32];
    int tid = threadIdx.x;
    for (int i = tid; i < F * 32; i += 256) sw[i] = W[i];
    long long r0 = (long long)blockIdx.x * 64;
    for (int i = tid; i < 64 * F; i += 256) {
        int r = i >> 6, c = i & 63;
        sx[r * F + c] = X[(r0 + r) * F + c];
    }
    __syncthreads();
    int h = tid & 31;
    int g = tid >> 5;
    float acc[8] = {0.f, 0.f, 0.f, 0.f, 0.f, 0.f, 0.f, 0.f};
    for (int f = 0; f < F; f++) {
        float w = sw[f * 32 + h];
#pragma unroll
        for (int i = 0; i < 8; i++)
            acc[i] = fmaf(sx[(g * 8 + i) * F + f], w, acc[i]);
    }
#pragma unroll
    for (int i = 0; i < 8; i++)
        Y[(r0 + g * 8 + i) * 32 + h] = __float2half(acc[i]);
}

// ===== agg1 fused with layer2 transform (known-good R3 form) =====
__global__ __launch_bounds__(512) void agg1_fuse_k(
    const __half* __restrict__ xw, const float* __restrict__ b1,
    const float* __restrict__ W2, __half* __restrict__ out2)
{
    __shared__ float sW2[32 * 32];
    int tid = threadIdx.x;
    for (int i = tid; i < 1024; i += 512) sW2[i] = W2[i];
    __syncthreads();

    int n = blockIdx.x;
    int b = tid >> 5;
    int lane = tid & 31;
    int beg = g_off[n], end = g_off[n + 1];
    const __half* xb = xw + (size_t)b * (Nn * Hh);
    float a0 = 0.f, a1 = 0.f, a2 = 0.f, a3 = 0.f;
    int e = beg;
    for (; e + 4 <= end; e += 4) {
        int s0 = g_srcs[e], s1 = g_srcs[e + 1], s2 = g_srcs[e + 2], s3 = g_srcs[e + 3];
        float m0 = g_nrms[e], m1 = g_nrms[e + 1], m2 = g_nrms[e + 2], m3 = g_nrms[e + 3];
        a0 = fmaf(m0, __half2float(xb[s0 * 32 + lane]), a0);
        a1 = fmaf(m1, __half2float(xb[s1 * 32 + lane]), a1);
        a2 = fmaf(m2, __half2float(xb[s2 * 32 + lane]), a2);
        a3 = fmaf(m3, __half2float(xb[s3 * 32 + lane]), a3);
    }
    for (; e < end; e++)
        a0 = fmaf(g_nrms[e], __half2float(xb[g_srcs[e] * 32 + lane]), a0);
    float h = fmaxf((a0 + a1) + (a2 + a3) + b1[lane], 0.0f);

    float o = 0.f;
#pragma unroll
    for (int f = 0; f < 32; f++) {
        float hf = __shfl_sync(0xffffffffu, h, f);
        o = fmaf(hf, sW2[f * 32 + lane], o);
    }
    out2[((size_t)b * Nn + n) * 32 + lane] = __float2half(o);
}

// ===== agg2: h2 = relu(agg(xw2) + b2), fp32 out (known-good R3 form) =====
__global__ __launch_bounds__(512) void agg2_k(
    const __half* __restrict__ xw, const float* __restrict__ bias,
    float* __restrict__ out)
{
    int n = blockIdx.x;
    int b = threadIdx.x >> 5;
    int lane = threadIdx.x & 31;
    int beg = g_off[n], end = g_off[n + 1];
    const __half* xb = xw + (size_t)b * (Nn * Hh);
    float a0 = 0.f, a1 = 0.f, a2 = 0.f, a3 = 0.f;
    int e = beg;
    for (; e + 4 <= end; e += 4) {
        int s0 = g_srcs[e], s1 = g_srcs[e + 1], s2 = g_srcs[e + 2], s3 = g_srcs[e + 3];
        float m0 = g_nrms[e], m1 = g_nrms[e + 1], m2 = g_nrms[e + 2], m3 = g_nrms[e + 3];
        a0 = fmaf(m0, __half2float(xb[s0 * 32 + lane]), a0);
        a1 = fmaf(m1, __half2float(xb[s1 * 32 + lane]), a1);
        a2 = fmaf(m2, __half2float(xb[s2 * 32 + lane]), a2);
        a3 = fmaf(m3, __half2float(xb[s3 * 32 + lane]), a3);
    }
    for (; e < end; e++)
        a0 = fmaf(g_nrms[e], __half2float(xb[g_srcs[e] * 32 + lane]), a0);
    float r = (a0 + a1) + (a2 + a3) + bias[lane];
    out[((size_t)b * Nn + n) * 32 + lane] = fmaxf(r, 0.0f);
}

// ===== big MLP GEMM: TMA bulk-copy 4-stage smem pipeline for weights =====
// One cp.async.bulk (32KB contiguous) per stage, issued by thread 0: kills the
// LDGSTS per-16B issue-rate wall. Weight DRAM traffic exactly 1x chip-wide.
__global__ __launch_bounds__(512) void mlp1_k(
    const float* __restrict__ flat, const float* __restrict__ Wp1)
{
    extern __shared__ __align__(16) unsigned char dsm[];
    float* wbuf = (float*)dsm;                               // NST*CH*512 floats
    unsigned long long* sbat =
        (unsigned long long*)(dsm + NST * STAGE_BYTES);      // [128][8] pairs
    unsigned mbar0 = smem_u32(dsm + NST * STAGE_BYTES + 128 * 8 * 8);
    unsigned wbuf0 = smem_u32(dsm);

    int tid = threadIdx.x;
    int kg = tid >> 7;                    // k-group 0..3 (rows ≡ kg mod 4)
    int c4 = (tid & 127) * 4;             // columns c4..c4+3
    int k0 = blockIdx.x * CHUNK;
    int k1 = min(k0 + CHUNK, Kdim);
    int nch = (k1 - k0 + CH - 1) / CH;    // always whole 16-row stages here

    if (tid == 0) {
#pragma unroll
        for (int s = 0; s < NST; s++)
            asm volatile("mbarrier.init.shared.b64 [%0], 1;"
                         :: "r"(mbar0 + s * 8) : "memory");
        asm volatile("fence.proxy.async.shared::cta;" ::: "memory");
    }
    __syncthreads();

#define ISSUE_STAGE(cc)                                                         \
    do {                                                                        \
        int _c = (cc);                                                          \
        if (_c < nch && tid == 0) {                                             \
            unsigned _mb = mbar0 + (_c & (NST - 1)) * 8;                        \
            asm volatile(                                                       \
                "mbarrier.arrive.expect_tx.shared.b64 _, [%0], %1;"             \
                :: "r"(_mb), "r"((unsigned)STAGE_BYTES) : "memory");            \
            unsigned _dst = wbuf0 + (_c & (NST - 1)) * STAGE_BYTES;             \
            const float* _src = Wp1 + (size_t)(k0 + _c * CH) * NHID;            \
            asm volatile(                                                       \
                "cp.async.bulk.shared::cta.global.mbarrier::complete_tx::bytes "\
                "[%0], [%1], %2, [%3];"                                         \
                :: "r"(_dst), "l"(_src), "r"((unsigned)STAGE_BYTES), "r"(_mb)   \
                : "memory");                                                    \
        }                                                                       \
    } while (0)

    unsigned long long acc[4][8];         // [col][batch-pair]
#pragma unroll
    for (int c = 0; c < 4; c++)
#pragma unroll
        for (int p = 0; p < 8; p++) acc[c][p] = 0ull;

    ISSUE_STAGE(0);
    ISSUE_STAGE(1);
    ISSUE_STAGE(2);

    for (int c = 0; c < nch; c++) {
        int kbase = k0 + c * CH;

        if ((c & 7) == 0) {
            // stage batch pairs for 128-row tile [kbase, kbase+128)
            int kt = kbase;
            int kn = min(128, k1 - kt);
#pragma unroll
            for (int idx = tid; idx < 1024; idx += 512) {
                int p = idx >> 7, kk = idx & 127;
                float a = 0.f, bv = 0.f;
                if (kk < kn) {
                    a  = flat[(size_t)(2 * p)     * Kdim + kt + kk];
                    bv = flat[(size_t)(2 * p + 1) * Kdim + kt + kk];
                }
                unsigned long long pr;
                asm("mov.b64 %0, {%1, %2};" : "=l"(pr)
                    : "r"(__float_as_uint(a)), "r"(__float_as_uint(bv)));
                sbat[kk * 8 + p] = pr;
            }
            __syncthreads();
        }

        // wait for stage c data (parity = use-count of slot & 1)
        mbar_wait_parity(mbar0 + (c & (NST - 1)) * 8, (unsigned)((c >> 2) & 1));

        // compute chunk c: rows kg, kg+4, kg+8, kg+12
        const float* wst = wbuf + (c & (NST - 1)) * (CH * NHID);
#pragma unroll
        for (int rr = 0; rr < 4; rr++) {
            int r = kg + rr * 4;
            float4 w = *(const float4*)(wst + r * NHID + c4);
            unsigned long long wd[4];
            asm("mov.b64 %0, {%1, %1};" : "=l"(wd[0]) : "r"(__float_as_uint(w.x)));
            asm("mov.b64 %0, {%1, %1};" : "=l"(wd[1]) : "r"(__float_as_uint(w.y)));
            asm("mov.b64 %0, {%1, %1};" : "=l"(wd[2]) : "r"(__float_as_uint(w.z)));
            asm("mov.b64 %0, {%1, %1};" : "=l"(wd[3]) : "r"(__float_as_uint(w.w)));
            int kk = (c & 7) * CH + r;
            const ulonglong2* f2 = (const ulonglong2*)(sbat + kk * 8);
#pragma unroll
            for (int q = 0; q < 4; q++) {
                ulonglong2 f = f2[q];       // broadcast LDS.128
#pragma unroll
                for (int cc = 0; cc < 4; cc++) {
                    asm("fma.rn.f32x2 %0, %1, %2, %0;"
                        : "+l"(acc[cc][2 * q])     : "l"(wd[cc]), "l"(f.x));
                    asm("fma.rn.f32x2 %0, %1, %2, %0;"
                        : "+l"(acc[cc][2 * q + 1]) : "l"(wd[cc]), "l"(f.y));
                }
            }
        }
        __syncthreads();          // all threads done reading slot (c & 3)
        ISSUE_STAGE(c + 3);       // refill slot (c+3)&3 == (c-1)&3
    }
#undef ISSUE_STAGE

#pragma unroll
    for (int cc = 0; cc < 4; cc++)
#pragma unroll
        for (int p = 0; p < 8; p++) {
            float2 v = *(float2*)&acc[cc][p];    // batches (2p,2p+1), col c4+cc
            atomicAdd(&g_hid[(2 * p)     * NHID + c4 + cc], v.x);
            atomicAdd(&g_hid[(2 * p + 1) * NHID + c4 + cc], v.y);
        }
}

// ===== final: relu(hid+bp1) @ Wp2 + bp2, one block per batch =====
__global__ __launch_bounds__(512) void mlp2_k(
    const float* __restrict__ bp1, const float* __restrict__ Wp2,
    const float* __restrict__ bp2, float* __restrict__ out)
{
    __shared__ float part[16][NACT];
    int b = blockIdx.x;
    int j = threadIdx.x;
    int wid = j >> 5, lane = j & 31;
    float hv = fmaxf(g_hid[b * NHID + j] + bp1[j], 0.0f);
    float acc[NACT];
#pragma unroll
    for (int a = 0; a < NACT; a++) acc[a] = hv * Wp2[j * NACT + a];
#pragma unroll
    for (int off = 16; off; off >>= 1)
#pragma unroll
        for (int a = 0; a < NACT; a++)
            acc[a] += __shfl_down_sync(0xffffffffu, acc[a], off);
    if (lane == 0)
#pragma unroll
        for (int a = 0; a < NACT; a++) part[wid][a] = acc[a];
    __syncthreads();
    if (j < NACT) {
        float s = bp2[j];
#pragma unroll
        for (int w = 0; w < 16; w++) s += part[w][j];
        out[b * NACT + j] = s;
    }
}

// ================= launch =================
extern "C" void kernel_launch(void* const* d_in, const int* in_sizes, int n_in,
                              void* d_out, int out_size)
{
    const float* features = (const float*)d_in[0];
    const void*  edge     = d_in[1];
    const float* W1  = (const float*)d_in[2];
    const float* b1  = (const float*)d_in[3];
    const float* W2  = (const float*)d_in[4];
    const float* b2  = (const float*)d_in[5];
    const float* Wp1 = (const float*)d_in[6];
    const float* bp1 = (const float*)d_in[7];
    const float* Wp2 = (const float*)d_in[8];
    const float* bp2 = (const float*)d_in[9];
    float* out = (float*)d_out;

    __half* xw1; cudaGetSymbolAddress((void**)&xw1, g_xw1);
    __half* xw2; cudaGetSymbolAddress((void**)&xw2, g_xw2);
    float*  h2;  cudaGetSymbolAddress((void**)&h2,  g_h2);

    init_k<<<(Bz * NHID + 255) / 256, 256>>>((const unsigned int*)edge);
    hist_k<<<(Ee + 255) / 256, 256>>>(edge);
    scan_k<<<1, 1024>>>();
    scatter_k<<<(ETOT + 255) / 256, 256>>>(edge);

    gemm1_k<<<(Bz * Nn) / 64, 256>>>(features, W1, xw1);
    agg1_fuse_k<<<Nn, 512>>>(xw1, b1, W2, xw2);
    agg2_k<<<Nn, 512>>>(xw2, b2, h2);

    size_t smem = (size_t)NST * STAGE_BYTES + 128 * 8 * 8 + 64;  // 131072+8192+64
    cudaFuncSetAttribute(mlp1_k, cudaFuncAttributeMaxDynamicSharedMemorySize,
                         (int)smem);
    mlp1_k<<<KSPLIT, 512, smem>>>(h2, Wp1);
    mlp2_k<<<Bz, 512>>>(bp1, Wp2, bp2, out);
}

// round 9
// speedup vs baseline: 1.6758x; 1.0073x over previous
#include <cuda_runtime.h>
#include <cuda_fp16.h>

// Problem constants
#define Bz 16
#define Nn 5000
#define Ff 64
#define Hh 32
#define Ee 160000
#define ETOT (Ee + Nn)         // edges + self loops = 165000
#define Kdim (Nn * Hh)         // 160000
#define NHID 512
#define NACT 16
#define KSPLIT 148
#define CHUNK 1088             // k-rows per block (multiple of 16), 148*1088 >= Kdim
#define CH 16                  // k-rows per TMA stage (32 KB contiguous)
#define NST 4                  // ring stages
#define STAGE_BYTES (CH * NHID * 4)   // 32768

// -------- scratch (device globals; no allocation allowed) --------
__device__ int    g_is64;
__device__ int    g_deg[Nn];
__device__ int    g_cursor[Nn];
__device__ int    g_off[Nn + 1];
__device__ float  g_dinv[Nn];
__device__ int    g_srcs[ETOT];
__device__ float  g_nrms[ETOT];
__device__ __half g_xw1[Bz * Nn * Hh];   // 5.12 MB
__device__ __half g_xw2[Bz * Nn * Hh];   // 5.12 MB
__device__ float  g_h2[Bz * Nn * Hh];    // 10.24 MB (MLP input)
__device__ float  g_hid[Bz * NHID];      // MLP hidden partials

__device__ __forceinline__ int edge_at(const void* ei, int idx) {
    if (g_is64) return (int)((const long long*)ei)[idx];
    return ((const int*)ei)[idx];
}

__device__ __forceinline__ unsigned smem_u32(const void* p) {
    unsigned a;
    asm("{ .reg .u64 t; cvta.to.shared.u64 t, %1; cvt.u32.u64 %0, t; }"
        : "=r"(a) : "l"(p));
    return a;
}

__device__ __forceinline__ void mbar_wait_parity(unsigned mbar, unsigned parity) {
    asm volatile(
        "{\n\t.reg .pred P;\n"
        "LW_%=:\n\t"
        "mbarrier.try_wait.parity.acquire.cta.shared::cta.b64 P, [%0], %1, 0x989680;\n\t"
        "@P bra LD_%=;\n\t"
        "bra LW_%=;\n"
        "LD_%=:\n\t}"
        :: "r"(mbar), "r"(parity) : "memory");
}

// ================= setup =================

__global__ void init_k(const unsigned int* __restrict__ ei) {
    int i = blockIdx.x * blockDim.x + threadIdx.x;
    if (i == 0) {
        int all0 = 1;
        for (int k = 0; k < 64; k++)
            if (ei[2 * k + 1] != 0u) { all0 = 0; break; }
        g_is64 = all0;
    }
    if (i < Nn) { g_deg[i] = 1; g_cursor[i] = 0; }
    if (i < Bz * NHID) g_hid[i] = 0.0f;
}

__global__ void hist_k(const void* __restrict__ ei) {
    int e = blockIdx.x * blockDim.x + threadIdx.x;
    if (e < Ee) atomicAdd(&g_deg[edge_at(ei, Ee + e)], 1);
}

// single block: dinv + exclusive scan of degrees (warp-shuffle based)
__global__ void scan_k() {
    __shared__ int wsum[32];
    int t = threadIdx.x, lane = t & 31, wid = t >> 5;
    const int CHD = 5;
    int base = t * CHD;
    int d[CHD];
    int local = 0;
#pragma unroll
    for (int j = 0; j < CHD; j++) {
        int idx = base + j;
        d[j] = (idx < Nn) ? g_deg[idx] : 0;
        local += d[j];
    }
    int incl = local;
#pragma unroll
    for (int off = 1; off < 32; off <<= 1) {
        int v = __shfl_up_sync(0xffffffffu, incl, off);
        if (lane >= off) incl += v;
    }
    if (lane == 31) wsum[wid] = incl;
    __syncthreads();
    if (wid == 0) {
        int iv = wsum[lane];
#pragma unroll
        for (int off = 1; off < 32; off <<= 1) {
            int u = __shfl_up_sync(0xffffffffu, iv, off);
            if (lane >= off) iv += u;
        }
        wsum[lane] = iv;
    }
    __syncthreads();
    int excl = (wid ? wsum[wid - 1] : 0) + (incl - local);
#pragma unroll
    for (int j = 0; j < CHD; j++) {
        int idx = base + j;
        if (idx < Nn) {
            g_off[idx] = excl;
            excl += d[j];
            g_dinv[idx] = rsqrtf((float)d[j]);
        }
    }
    if (t == 1023) g_off[Nn] = wsum[31];
}

__global__ void scatter_k(const void* __restrict__ ei) {
    int i = blockIdx.x * blockDim.x + threadIdx.x;
    if (i >= ETOT) return;
    int s, d;
    if (i < Ee) { s = edge_at(ei, i); d = edge_at(ei, Ee + i); }
    else        { s = d = i - Ee; }
    float nm = g_dinv[s] * g_dinv[d];
    int pos = g_off[d] + atomicAdd(&g_cursor[d], 1);
    g_srcs[pos] = s;
    g_nrms[pos] = nm;
}

// ============ layer1 GEMM: xw1[r,32] = feat[r,64] @ W1, fp16 out ============
__global__ __launch_bounds__(256) void gemm1_k(
    const float* __restrict__ X, const float* __restrict__ W,
    __half* __restrict__ Y)
{
    const int F = Ff;
    __shared__ float sx[64 * Ff];
    __shared__ float sw[Ff * 32];
    int tid = threadIdx.x;
    for (int i = tid; i < F * 32; i += 256) sw[i] = W[i];
    long long r0 = (long long)blockIdx.x * 64;
    for (int i = tid; i < 64 * F; i += 256) {
        int r = i >> 6, c = i & 63;
        sx[r * F + c] = X[(r0 + r) * F + c];
    }
    __syncthreads();
    int h = tid & 31;
    int g = tid >> 5;
    float acc[8] = {0.f, 0.f, 0.f, 0.f, 0.f, 0.f, 0.f, 0.f};
    for (int f = 0; f < F; f++) {
        float w = sw[f * 32 + h];
#pragma unroll
        for (int i = 0; i < 8; i++)
            acc[i] = fmaf(sx[(g * 8 + i) * F + f], w, acc[i]);
    }
#pragma unroll
    for (int i = 0; i < 8; i++)
        Y[(r0 + g * 8 + i) * 32 + h] = __float2half(acc[i]);
}

// ===== agg1 fused with layer2 transform: ILP-8 gathers, 256 thr, grid (Nn,2) =====
//   h1 = relu(agg(xw1) + b1); xw2 = h1 @ W2   (warp = one (node,batch) row)
__global__ __launch_bounds__(256) void agg1_fuse_k(
    const __half* __restrict__ xw, const float* __restrict__ b1,
    const float* __restrict__ W2, __half* __restrict__ out2)
{
    __shared__ float sW2[32 * 32];
    int tid = threadIdx.x;
    for (int i = tid; i < 1024; i += 256) sW2[i] = W2[i];
    __syncthreads();

    int n = blockIdx.x;
    int b = blockIdx.y * 8 + (tid >> 5);
    int lane = tid & 31;
    int beg = g_off[n], end = g_off[n + 1];
    const __half* xb = xw + (size_t)b * (Nn * Hh);

    float a[8] = {0.f, 0.f, 0.f, 0.f, 0.f, 0.f, 0.f, 0.f};
    int e = beg;
    for (; e + 8 <= end; e += 8) {
        int   s[8];
        float m[8];
#pragma unroll
        for (int q = 0; q < 8; q++) { s[q] = g_srcs[e + q]; m[q] = g_nrms[e + q]; }
#pragma unroll
        for (int q = 0; q < 8; q++)
            a[q] = fmaf(m[q], __half2float(xb[s[q] * 32 + lane]), a[q]);
    }
    for (; e < end; e++)
        a[0] = fmaf(g_nrms[e], __half2float(xb[g_srcs[e] * 32 + lane]), a[0]);
    float h = ((a[0] + a[1]) + (a[2] + a[3])) + ((a[4] + a[5]) + (a[6] + a[7]));
    h = fmaxf(h + b1[lane], 0.0f);

    // xw2 row = h1row @ W2 via lane broadcast
    float o = 0.f;
#pragma unroll
    for (int f = 0; f < 32; f++) {
        float hf = __shfl_sync(0xffffffffu, h, f);
        o = fmaf(hf, sW2[f * 32 + lane], o);
    }
    out2[((size_t)b * Nn + n) * 32 + lane] = __float2half(o);
}

// ===== agg2: h2 = relu(agg(xw2) + b2), fp32 out; ILP-8, 256 thr, grid (Nn,2) =====
__global__ __launch_bounds__(256) void agg2_k(
    const __half* __restrict__ xw, const float* __restrict__ bias,
    float* __restrict__ out)
{
    int n = blockIdx.x;
    int b = blockIdx.y * 8 + (threadIdx.x >> 5);
    int lane = threadIdx.x & 31;
    int beg = g_off[n], end = g_off[n + 1];
    const __half* xb = xw + (size_t)b * (Nn * Hh);

    float a[8] = {0.f, 0.f, 0.f, 0.f, 0.f, 0.f, 0.f, 0.f};
    int e = beg;
    for (; e + 8 <= end; e += 8) {
        int   s[8];
        float m[8];
#pragma unroll
        for (int q = 0; q < 8; q++) { s[q] = g_srcs[e + q]; m[q] = g_nrms[e + q]; }
#pragma unroll
        for (int q = 0; q < 8; q++)
            a[q] = fmaf(m[q], __half2float(xb[s[q] * 32 + lane]), a[q]);
    }
    for (; e < end; e++)
        a[0] = fmaf(g_nrms[e], __half2float(xb[g_srcs[e] * 32 + lane]), a[0]);
    float r = ((a[0] + a[1]) + (a[2] + a[3])) + ((a[4] + a[5]) + (a[6] + a[7]));
    r += bias[lane];
    out[((size_t)b * Nn + n) * 32 + lane] = fmaxf(r, 0.0f);
}

// ===== big MLP GEMM: TMA bulk-copy 4-stage smem pipeline for weights =====
__global__ __launch_bounds__(512) void mlp1_k(
    const float* __restrict__ flat, const float* __restrict__ Wp1)
{
    extern __shared__ __align__(16) unsigned char dsm[];
    float* wbuf = (float*)dsm;                               // NST*CH*512 floats
    unsigned long long* sbat =
        (unsigned long long*)(dsm + NST * STAGE_BYTES);      // [128][8] pairs
    unsigned mbar0 = smem_u32(dsm + NST * STAGE_BYTES + 128 * 8 * 8);
    unsigned wbuf0 = smem_u32(dsm);

    int tid = threadIdx.x;
    int kg = tid >> 7;                    // k-group 0..3 (rows ≡ kg mod 4)
    int c4 = (tid & 127) * 4;             // columns c4..c4+3
    int k0 = blockIdx.x * CHUNK;
    int k1 = min(k0 + CHUNK, Kdim);
    int nch = (k1 - k0 + CH - 1) / CH;

    if (tid == 0) {
#pragma unroll
        for (int s = 0; s < NST; s++)
            asm volatile("mbarrier.init.shared.b64 [%0], 1;"
                         :: "r"(mbar0 + s * 8) : "memory");
        asm volatile("fence.proxy.async.shared::cta;" ::: "memory");
    }
    __syncthreads();

#define ISSUE_STAGE(cc)                                                         \
    do {                                                                        \
        int _c = (cc);                                                          \
        if (_c < nch && tid == 0) {                                             \
            unsigned _mb = mbar0 + (_c & (NST - 1)) * 8;                        \
            asm volatile(                                                       \
                "mbarrier.arrive.expect_tx.shared.b64 _, [%0], %1;"             \
                :: "r"(_mb), "r"((unsigned)STAGE_BYTES) : "memory");            \
            unsigned _dst = wbuf0 + (_c & (NST - 1)) * STAGE_BYTES;             \
            const float* _src = Wp1 + (size_t)(k0 + _c * CH) * NHID;            \
            asm volatile(                                                       \
                "cp.async.bulk.shared::cta.global.mbarrier::complete_tx::bytes "\
                "[%0], [%1], %2, [%3];"                                         \
                :: "r"(_dst), "l"(_src), "r"((unsigned)STAGE_BYTES), "r"(_mb)   \
                : "memory");                                                    \
        }                                                                       \
    } while (0)

    unsigned long long acc[4][8];         // [col][batch-pair]
#pragma unroll
    for (int c = 0; c < 4; c++)
#pragma unroll
        for (int p = 0; p < 8; p++) acc[c][p] = 0ull;

    ISSUE_STAGE(0);
    ISSUE_STAGE(1);
    ISSUE_STAGE(2);

    for (int c = 0; c < nch; c++) {
        int kbase = k0 + c * CH;

        if ((c & 7) == 0) {
            int kt = kbase;
            int kn = min(128, k1 - kt);
#pragma unroll
            for (int idx = tid; idx < 1024; idx += 512) {
                int p = idx >> 7, kk = idx & 127;
                float a = 0.f, bv = 0.f;
                if (kk < kn) {
                    a  = flat[(size_t)(2 * p)     * Kdim + kt + kk];
                    bv = flat[(size_t)(2 * p + 1) * Kdim + kt + kk];
                }
                unsigned long long pr;
                asm("mov.b64 %0, {%1, %2};" : "=l"(pr)
                    : "r"(__float_as_uint(a)), "r"(__float_as_uint(bv)));
                sbat[kk * 8 + p] = pr;
            }
            __syncthreads();
        }

        mbar_wait_parity(mbar0 + (c & (NST - 1)) * 8, (unsigned)((c >> 2) & 1));

        const float* wst = wbuf + (c & (NST - 1)) * (CH * NHID);
#pragma unroll
        for (int rr = 0; rr < 4; rr++) {
            int r = kg + rr * 4;
            float4 w = *(const float4*)(wst + r * NHID + c4);
            unsigned long long wd[4];
            asm("mov.b64 %0, {%1, %1};" : "=l"(wd[0]) : "r"(__float_as_uint(w.x)));
            asm("mov.b64 %0, {%1, %1};" : "=l"(wd[1]) : "r"(__float_as_uint(w.y)));
            asm("mov.b64 %0, {%1, %1};" : "=l"(wd[2]) : "r"(__float_as_uint(w.z)));
            asm("mov.b64 %0, {%1, %1};" : "=l"(wd[3]) : "r"(__float_as_uint(w.w)));
            int kk = (c & 7) * CH + r;
            const ulonglong2* f2 = (const ulonglong2*)(sbat + kk * 8);
#pragma unroll
            for (int q = 0; q < 4; q++) {
                ulonglong2 f = f2[q];
#pragma unroll
                for (int cc = 0; cc < 4; cc++) {
                    asm("fma.rn.f32x2 %0, %1, %2, %0;"
                        : "+l"(acc[cc][2 * q])     : "l"(wd[cc]), "l"(f.x));
                    asm("fma.rn.f32x2 %0, %1, %2, %0;"
                        : "+l"(acc[cc][2 * q + 1]) : "l"(wd[cc]), "l"(f.y));
                }
            }
        }
        __syncthreads();
        ISSUE_STAGE(c + 3);
    }
#undef ISSUE_STAGE

#pragma unroll
    for (int cc = 0; cc < 4; cc++)
#pragma unroll
        for (int p = 0; p < 8; p++) {
            float2 v = *(float2*)&acc[cc][p];
            atomicAdd(&g_hid[(2 * p)     * NHID + c4 + cc], v.x);
            atomicAdd(&g_hid[(2 * p + 1) * NHID + c4 + cc], v.y);
        }
}

// ===== final: relu(hid+bp1) @ Wp2 + bp2, one block per batch =====
__global__ __launch_bounds__(512) void mlp2_k(
    const float* __restrict__ bp1, const float* __restrict__ Wp2,
    const float* __restrict__ bp2, float* __restrict__ out)
{
    __shared__ float part[16][NACT];
    int b = blockIdx.x;
    int j = threadIdx.x;
    int wid = j >> 5, lane = j & 31;
    float hv = fmaxf(g_hid[b * NHID + j] + bp1[j], 0.0f);
    float acc[NACT];
#pragma unroll
    for (int a = 0; a < NACT; a++) acc[a] = hv * Wp2[j * NACT + a];
#pragma unroll
    for (int off = 16; off; off >>= 1)
#pragma unroll
        for (int a = 0; a < NACT; a++)
            acc[a] += __shfl_down_sync(0xffffffffu, acc[a], off);
    if (lane == 0)
#pragma unroll
        for (int a = 0; a < NACT; a++) part[wid][a] = acc[a];
    __syncthreads();
    if (j < NACT) {
        float s = bp2[j];
#pragma unroll
        for (int w = 0; w < 16; w++) s += part[w][j];
        out[b * NACT + j] = s;
    }
}

// ================= launch =================
extern "C" void kernel_launch(void* const* d_in, const int* in_sizes, int n_in,
                              void* d_out, int out_size)
{
    const float* features = (const float*)d_in[0];
    const void*  edge     = d_in[1];
    const float* W1  = (const float*)d_in[2];
    const float* b1  = (const float*)d_in[3];
    const float* W2  = (const float*)d_in[4];
    const float* b2  = (const float*)d_in[5];
    const float* Wp1 = (const float*)d_in[6];
    const float* bp1 = (const float*)d_in[7];
    const float* Wp2 = (const float*)d_in[8];
    const float* bp2 = (const float*)d_in[9];
    float* out = (float*)d_out;

    __half* xw1; cudaGetSymbolAddress((void**)&xw1, g_xw1);
    __half* xw2; cudaGetSymbolAddress((void**)&xw2, g_xw2);
    float*  h2;  cudaGetSymbolAddress((void**)&h2,  g_h2);

    init_k<<<(Bz * NHID + 255) / 256, 256>>>((const unsigned int*)edge);
    hist_k<<<(Ee + 255) / 256, 256>>>(edge);
    scan_k<<<1, 1024>>>();
    scatter_k<<<(ETOT + 255) / 256, 256>>>(edge);

    gemm1_k<<<(Bz * Nn) / 64, 256>>>(features, W1, xw1);
    dim3 agrid(Nn, 2);
    agg1_fuse_k<<<agrid, 256>>>(xw1, b1, W2, xw2);
    agg2_k<<<agrid, 256>>>(xw2, b2, h2);

    size_t smem = (size_t)NST * STAGE_BYTES + 128 * 8 * 8 + 64;  // 131072+8192+64
    cudaFuncSetAttribute(mlp1_k, cudaFuncAttributeMaxDynamicSharedMemorySize,
                         (int)smem);
    mlp1_k<<<KSPLIT, 512, smem>>>(h2, Wp1);
    mlp2_k<<<Bz, 512>>>(bp1, Wp2, bp2, out);
}